// round 2
// baseline (speedup 1.0000x reference)
#include <cuda_runtime.h>
#include <cuda_bf16.h>
#include <cstdint>
#include <math.h>

// ---------------------------------------------------------------------------
// Problem constants (fixed by the dataset)
// ---------------------------------------------------------------------------
#define NN 50000      // nodes per type
#define EE 200000     // edges per relation
#define RR 4
#define TT 2
#define HH 8
#define DKK 16
#define OUTD 128

// REL = [(0,1),(1,0),(0,0),(1,1)]  -> st = r&1 ; dt = (r==0||r==3)?1:0
// dst type 0 receives relations {1,2}; dst type 1 receives {0,3}

// ---------------------------------------------------------------------------
// One big device scratch buffer (no allocations allowed)
// ---------------------------------------------------------------------------
constexpr size_t OFF_K     = 0;                               // 4*NN*128  (reused as NUM after pass A)
constexpr size_t OFF_NUM   = OFF_K;
constexpr size_t OFF_V     = OFF_K     + (size_t)4*NN*128;    // 4*NN*128
constexpr size_t OFF_Q     = OFF_V     + (size_t)4*NN*128;    // 2*NN*128  (reused as AGG after pass B)
constexpr size_t OFF_SCORE = OFF_Q     + (size_t)2*NN*128;    // 4*EE*8
constexpr size_t OFF_MAX   = OFF_SCORE + (size_t)4*EE*8;      // 4*NN*8
constexpr size_t OFF_DEN   = OFF_MAX   + (size_t)4*NN*8;      // 4*NN*8
constexpr size_t OFF_TRANS = OFF_DEN   + (size_t)4*NN*8;      // 2*NN*128
constexpr size_t OFF_WKE   = OFF_TRANS + (size_t)2*NN*128;    // 4*128*128
constexpr size_t OFF_WVE   = OFF_WKE   + (size_t)4*128*128;
constexpr size_t OFF_BKE   = OFF_WVE   + (size_t)4*128*128;   // 4*128
constexpr size_t OFF_BVE   = OFF_BKE   + (size_t)4*128;
constexpr size_t BUF_TOTAL = OFF_BVE   + (size_t)4*128;

__device__ float g_buf[BUF_TOTAL];

// ---------------------------------------------------------------------------
// Small helpers
// ---------------------------------------------------------------------------
__device__ __forceinline__ void atomicMaxF(float* addr, float val) {
    int* ia = (int*)addr;
    int old = *ia;
    while (__int_as_float(old) < val) {
        int assumed = old;
        old = atomicCAS(ia, assumed, __float_as_int(val));
        if (old == assumed) break;
    }
}

// init max (-inf) and den (0) in one launch; the two regions are adjacent.
__global__ void init_maxden_kernel() {
    size_t n = (size_t)4 * NN * 8;
    size_t i = (size_t)blockIdx.x * blockDim.x + threadIdx.x;
    size_t stride = (size_t)gridDim.x * blockDim.x;
    for (; i < n; i += stride) {
        g_buf[OFF_MAX + i] = -INFINITY;
        g_buf[OFF_DEN + i] = 0.f;
    }
}

__global__ void zero_num_kernel() {
    size_t n = (size_t)4 * NN * 128;
    size_t i = (size_t)blockIdx.x * blockDim.x + threadIdx.x;
    size_t stride = (size_t)gridDim.x * blockDim.x;
    for (; i < n; i += stride) g_buf[OFF_NUM + i] = 0.f;
}

// ---------------------------------------------------------------------------
// Fold rel_att / rel_msg into effective per-relation weights:
// WkEff[r][i][h*16+e] = sum_d Wk[st][i][h*16+d] * rel_att[r][h][d][e]
// ---------------------------------------------------------------------------
__global__ void prep_weights(const float* __restrict__ Wk, const float* __restrict__ bk,
                             const float* __restrict__ Wv, const float* __restrict__ bv,
                             const float* __restrict__ rel_att, const float* __restrict__ rel_msg) {
    int idx = blockIdx.x * blockDim.x + threadIdx.x;
    if (idx >= 4 * 128 * 128) return;
    int r  = idx >> 14;
    int i  = (idx >> 7) & 127;
    int o  = idx & 127;
    int h  = o >> 4;
    int eo = o & 15;
    int st = r & 1;
    const float* wkp = Wk + (size_t)st * 16384 + (size_t)i * 128 + h * 16;
    const float* wvp = Wv + (size_t)st * 16384 + (size_t)i * 128 + h * 16;
    const float* rap = rel_att + (((size_t)r * 8 + h) * 16) * 16 + eo;
    const float* rmp = rel_msg + (((size_t)r * 8 + h) * 16) * 16 + eo;
    float ak = 0.f, av = 0.f;
#pragma unroll
    for (int d = 0; d < 16; d++) {
        ak += wkp[d] * rap[d * 16];
        av += wvp[d] * rmp[d * 16];
    }
    g_buf[OFF_WKE + (size_t)r * 16384 + (size_t)i * 128 + o] = ak;
    g_buf[OFF_WVE + (size_t)r * 16384 + (size_t)i * 128 + o] = av;
    if (i == 0) {
        const float* bkp = bk + st * 128 + h * 16;
        const float* bvp = bv + st * 128 + h * 16;
        float sk = 0.f, sv = 0.f;
#pragma unroll
        for (int d = 0; d < 16; d++) {
            sk += bkp[d] * rap[d * 16];
            sv += bvp[d] * rmp[d * 16];
        }
        g_buf[OFF_BKE + r * 128 + o] = sk;
        g_buf[OFF_BVE + r * 128 + o] = sv;
    }
}

// ---------------------------------------------------------------------------
// fp32 GEMM: C[M,128] = A[M,128] @ W[128,128] + bias
// BM=64, BN=128, BK=32, 256 threads, 4x8 per-thread tile.
// ---------------------------------------------------------------------------
#define GBM 64
#define GBN 128
#define GBK 32

__global__ __launch_bounds__(256) void gemm128(const float* __restrict__ A,
                                               const float* __restrict__ W,
                                               const float* __restrict__ bias,
                                               float* __restrict__ C, int M) {
    __shared__ float As[GBK][GBM + 4];   // transposed A tile; +4 keeps float4 alignment
    __shared__ float Ws[GBK][GBN];

    int tid = threadIdx.x;
    int tx = tid & 15;   // column group (8 cols each)
    int ty = tid >> 4;   // row group (4 rows each)
    int m0 = blockIdx.x * GBM;

    float acc[4][8];
#pragma unroll
    for (int r = 0; r < 4; r++)
#pragma unroll
        for (int c = 0; c < 8; c++) acc[r][c] = 0.f;

    for (int kb = 0; kb < 128; kb += GBK) {
        // Load A tile: 64 rows x 32 cols -> 512 float4, 2 per thread (coalesced)
#pragma unroll
        for (int i = 0; i < 2; i++) {
            int f   = i * 256 + tid;        // 0..511
            int row = f >> 3;               // 8 float4 per row
            int cg  = f & 7;
            int m   = m0 + row;
            float4 v = make_float4(0.f, 0.f, 0.f, 0.f);
            if (m < M) v = *(const float4*)&A[(size_t)m * 128 + kb + cg * 4];
            As[cg * 4 + 0][row] = v.x;
            As[cg * 4 + 1][row] = v.y;
            As[cg * 4 + 2][row] = v.z;
            As[cg * 4 + 3][row] = v.w;
        }
        // Load W tile: 32 x 128 -> 1024 float4, 4 per thread (coalesced)
#pragma unroll
        for (int i = 0; i < 4; i++) {
            int f  = i * 256 + tid;         // 0..1023
            int k  = f >> 5;                // 32 float4 per row
            int cg = f & 31;
            *(float4*)&Ws[k][cg * 4] = *(const float4*)&W[(size_t)(kb + k) * 128 + cg * 4];
        }
        __syncthreads();

#pragma unroll
        for (int k = 0; k < GBK; k++) {
            float4 a  = *(const float4*)&As[k][ty * 4];
            float4 w0 = *(const float4*)&Ws[k][tx * 8];
            float4 w1 = *(const float4*)&Ws[k][tx * 8 + 4];
            float av[4] = {a.x, a.y, a.z, a.w};
            float wv[8] = {w0.x, w0.y, w0.z, w0.w, w1.x, w1.y, w1.z, w1.w};
#pragma unroll
            for (int r = 0; r < 4; r++)
#pragma unroll
                for (int c = 0; c < 8; c++) acc[r][c] += av[r] * wv[c];
        }
        __syncthreads();
    }

    // Epilogue: add bias, write
    float b0x = bias[tx * 8 + 0], b0y = bias[tx * 8 + 1], b0z = bias[tx * 8 + 2], b0w = bias[tx * 8 + 3];
    float b1x = bias[tx * 8 + 4], b1y = bias[tx * 8 + 5], b1z = bias[tx * 8 + 6], b1w = bias[tx * 8 + 7];
#pragma unroll
    for (int r = 0; r < 4; r++) {
        int m = m0 + ty * 4 + r;
        if (m < M) {
            float4 o0 = make_float4(acc[r][0] + b0x, acc[r][1] + b0y, acc[r][2] + b0z, acc[r][3] + b0w);
            float4 o1 = make_float4(acc[r][4] + b1x, acc[r][5] + b1y, acc[r][6] + b1z, acc[r][7] + b1w);
            *(float4*)&C[(size_t)m * 128 + tx * 8]     = o0;
            *(float4*)&C[(size_t)m * 128 + tx * 8 + 4] = o1;
        }
    }
}

// ---------------------------------------------------------------------------
// Pass A: per-edge attention scores + per-(dst,head) max.  One warp per edge.
// ---------------------------------------------------------------------------
__global__ void passA(const float* __restrict__ pri,
                      const int* __restrict__ s0, const int* __restrict__ d0,
                      const int* __restrict__ s1, const int* __restrict__ d1,
                      const int* __restrict__ s2, const int* __restrict__ d2,
                      const int* __restrict__ s3, const int* __restrict__ d3,
                      int E) {
    int r = blockIdx.y;
    int e = blockIdx.x * (blockDim.x >> 5) + (threadIdx.x >> 5);
    if (e >= E) return;
    int lane = threadIdx.x & 31;

    const int* src = (r == 0) ? s0 : (r == 1) ? s1 : (r == 2) ? s2 : s3;
    const int* dst = (r == 0) ? d0 : (r == 1) ? d1 : (r == 2) ? d2 : d3;
    int dt = (r == 0 || r == 3) ? 1 : 0;

    int s = src[e];
    int d = dst[e];

    const float* Q = g_buf + OFF_Q + ((size_t)dt * NN + d) * 128;
    const float* K = g_buf + OFF_K + ((size_t)r  * NN + s) * 128;
    float4 q = *(const float4*)&Q[lane * 4];
    float4 k = *(const float4*)&K[lane * 4];
    float p = q.x * k.x + q.y * k.y + q.z * k.z + q.w * k.w;
    // reduce within each group of 4 lanes (one head = 16 floats = 4 lanes)
    p += __shfl_xor_sync(0xffffffffu, p, 1);
    p += __shfl_xor_sync(0xffffffffu, p, 2);
    int h = lane >> 2;
    float sc = p * pri[r * 8 + h] * 0.25f;   // 1/sqrt(16)

    if ((lane & 3) == 0) {
        g_buf[OFF_SCORE + ((size_t)r * EE + e) * 8 + h] = sc;
        atomicMaxF(&g_buf[OFF_MAX + ((size_t)r * NN + d) * 8 + h], sc);
    }
}

// ---------------------------------------------------------------------------
// Pass B: ex = exp(score - max), accumulate den and unnormalized numerator.
// One warp per edge. Numerator normalization happens at node level later.
// ---------------------------------------------------------------------------
__global__ void passB(const int* __restrict__ s0, const int* __restrict__ d0,
                      const int* __restrict__ s1, const int* __restrict__ d1,
                      const int* __restrict__ s2, const int* __restrict__ d2,
                      const int* __restrict__ s3, const int* __restrict__ d3,
                      int E) {
    int r = blockIdx.y;
    int e = blockIdx.x * (blockDim.x >> 5) + (threadIdx.x >> 5);
    if (e >= E) return;
    int lane = threadIdx.x & 31;

    const int* src = (r == 0) ? s0 : (r == 1) ? s1 : (r == 2) ? s2 : s3;
    const int* dst = (r == 0) ? d0 : (r == 1) ? d1 : (r == 2) ? d2 : d3;

    int s = src[e];
    int d = dst[e];
    int h = lane >> 2;

    float sc = g_buf[OFF_SCORE + ((size_t)r * EE + e) * 8 + h];
    float mx = g_buf[OFF_MAX + ((size_t)r * NN + d) * 8 + h];
    float ex = __expf(sc - mx);

    if ((lane & 3) == 0)
        atomicAdd(&g_buf[OFF_DEN + ((size_t)r * NN + d) * 8 + h], ex);

    float4 v = *(const float4*)&g_buf[OFF_V + ((size_t)r * NN + s) * 128 + lane * 4];
    float* np = g_buf + OFF_NUM + ((size_t)r * NN + d) * 128 + lane * 4;
    atomicAdd(np + 0, v.x * ex);
    atomicAdd(np + 1, v.y * ex);
    atomicAdd(np + 2, v.z * ex);
    atomicAdd(np + 3, v.w * ex);
}

// ---------------------------------------------------------------------------
// Node-level aggregation: agg[t][n][j] = 0.5 * sum over the 2 relations
// targeting type t of num[r]/den[r]   (0 if den==0, i.e. no edges).
// ---------------------------------------------------------------------------
__global__ void agg_kernel() {
    size_t total = (size_t)2 * NN * 128;
    size_t i = (size_t)blockIdx.x * blockDim.x + threadIdx.x;
    size_t stride = (size_t)gridDim.x * blockDim.x;
    for (; i < total; i += stride) {
        int j = (int)(i & 127);
        size_t nt = i >> 7;
        int t = (int)(nt / NN);
        int n = (int)(nt % NN);
        int rA = (t == 0) ? 1 : 0;
        int rB = (t == 0) ? 2 : 3;
        int h = j >> 4;
        float a = 0.f;
        float dA = g_buf[OFF_DEN + ((size_t)rA * NN + n) * 8 + h];
        if (dA > 0.f) a += g_buf[OFF_NUM + ((size_t)rA * NN + n) * 128 + j] / dA;
        float dB = g_buf[OFF_DEN + ((size_t)rB * NN + n) * 8 + h];
        if (dB > 0.f) a += g_buf[OFF_NUM + ((size_t)rB * NN + n) * 128 + j] / dB;
        g_buf[OFF_Q + i] = 0.5f * a;    // Q region reused as agg
    }
}

// ---------------------------------------------------------------------------
// Skip connection + LayerNorm.  One warp per row.
// ---------------------------------------------------------------------------
__global__ void ln_kernel(const float* __restrict__ h0, const float* __restrict__ h1,
                          const float* __restrict__ skip,
                          const float* __restrict__ ln_g, const float* __restrict__ ln_b,
                          float* __restrict__ out) {
    int warp = (blockIdx.x * blockDim.x + threadIdx.x) >> 5;
    int lane = threadIdx.x & 31;
    if (warp >= 2 * NN) return;
    int t = warp / NN;
    int n = warp % NN;

    const float* hh = (t == 0) ? h0 : h1;
    const float* tr = g_buf + OFF_TRANS + ((size_t)t * NN + n) * 128;
    float alpha = 1.f / (1.f + __expf(-skip[t]));
    float beta = 1.f - alpha;

    float4 tv = *(const float4*)&tr[lane * 4];
    float4 hv = *(const float4*)&hh[(size_t)n * 128 + lane * 4];
    float4 x;
    x.x = tv.x * alpha + hv.x * beta;
    x.y = tv.y * alpha + hv.y * beta;
    x.z = tv.z * alpha + hv.z * beta;
    x.w = tv.w * alpha + hv.w * beta;

    float s1 = x.x + x.y + x.z + x.w;
    float s2 = x.x * x.x + x.y * x.y + x.z * x.z + x.w * x.w;
#pragma unroll
    for (int o = 16; o >= 1; o >>= 1) {
        s1 += __shfl_xor_sync(0xffffffffu, s1, o);
        s2 += __shfl_xor_sync(0xffffffffu, s2, o);
    }
    float mean = s1 * (1.f / 128.f);
    float var  = s2 * (1.f / 128.f) - mean * mean;
    float rstd = rsqrtf(var + 1e-5f);

    int j = lane * 4;
    float4 g4 = *(const float4*)&ln_g[t * 128 + j];
    float4 b4 = *(const float4*)&ln_b[t * 128 + j];
    float4 o4;
    o4.x = (x.x - mean) * rstd * g4.x + b4.x;
    o4.y = (x.y - mean) * rstd * g4.y + b4.y;
    o4.z = (x.z - mean) * rstd * g4.z + b4.z;
    o4.w = (x.w - mean) * rstd * g4.w + b4.w;
    *(float4*)&out[((size_t)t * NN + n) * 128 + j] = o4;
}

// ---------------------------------------------------------------------------
// Host launcher
// ---------------------------------------------------------------------------
extern "C" void kernel_launch(void* const* d_in, const int* in_sizes, int n_in,
                              void* d_out, int out_size) {
    const float* h0 = (const float*)d_in[0];
    const float* h1 = (const float*)d_in[1];
    const int* s0 = (const int*)d_in[2];
    const int* d0 = (const int*)d_in[3];
    const int* s1 = (const int*)d_in[4];
    const int* d1 = (const int*)d_in[5];
    const int* s2 = (const int*)d_in[6];
    const int* d2 = (const int*)d_in[7];
    const int* s3 = (const int*)d_in[8];
    const int* d3 = (const int*)d_in[9];
    const float* Wk = (const float*)d_in[10];
    const float* bk = (const float*)d_in[11];
    const float* Wq = (const float*)d_in[12];
    const float* bq = (const float*)d_in[13];
    const float* Wv = (const float*)d_in[14];
    const float* bv = (const float*)d_in[15];
    const float* Wa = (const float*)d_in[16];
    const float* ba = (const float*)d_in[17];
    const float* rel_att = (const float*)d_in[18];
    const float* rel_msg = (const float*)d_in[19];
    const float* rel_pri = (const float*)d_in[20];
    const float* skip = (const float*)d_in[21];
    const float* ln_g = (const float*)d_in[22];
    const float* ln_b = (const float*)d_in[23];

    // Resolve the scratch symbol once (deterministic; avoids repeated runtime
    // API calls during graph capture).
    static float* buf = nullptr;
    if (!buf) cudaGetSymbolAddress((void**)&buf, g_buf);

    const float* hs[2] = {h0, h1};
    const int ST[4] = {0, 1, 0, 1};

    // 1) fold relation transforms into effective weights
    prep_weights<<<(4 * 128 * 128 + 255) / 256, 256>>>(Wk, bk, Wv, bv, rel_att, rel_msg);

    // 2) init max (-inf) / den (0)
    init_maxden_kernel<<<512, 256>>>();

    // 3) projections (10 GEMMs of [NN,128]x[128,128])
    int gblocks = (NN + GBM - 1) / GBM;
    for (int r = 0; r < 4; r++) {
        gemm128<<<gblocks, 256>>>(hs[ST[r]], buf + OFF_WKE + (size_t)r * 16384,
                                  buf + OFF_BKE + r * 128,
                                  buf + OFF_K + (size_t)r * NN * 128, NN);
        gemm128<<<gblocks, 256>>>(hs[ST[r]], buf + OFF_WVE + (size_t)r * 16384,
                                  buf + OFF_BVE + r * 128,
                                  buf + OFF_V + (size_t)r * NN * 128, NN);
    }
    for (int t = 0; t < 2; t++) {
        gemm128<<<gblocks, 256>>>(hs[t], Wq + (size_t)t * 16384, bq + t * 128,
                                  buf + OFF_Q + (size_t)t * NN * 128, NN);
    }

    // 4) pass A: scores + segment max
    dim3 gA((EE + 7) / 8, 4);
    passA<<<gA, 256>>>(rel_pri, s0, d0, s1, d1, s2, d2, s3, d3, EE);

    // 5) zero numerator region (aliases K, which is dead after pass A)
    zero_num_kernel<<<2048, 256>>>();

    // 6) pass B: exp + den + numerator scatter
    passB<<<gA, 256>>>(s0, d0, s1, d1, s2, d2, s3, d3, EE);

    // 7) node-level normalization + cross-relation mean (writes agg into Q region)
    agg_kernel<<<2048, 256>>>();

    // 8) output projection
    for (int t = 0; t < 2; t++) {
        gemm128<<<gblocks, 256>>>(buf + OFF_Q + (size_t)t * NN * 128,
                                  Wa + (size_t)t * 16384, ba + t * 128,
                                  buf + OFF_TRANS + (size_t)t * NN * 128, NN);
    }

    // 9) skip + layernorm -> d_out
    ln_kernel<<<(2 * NN * 32 + 255) / 256, 256>>>(h0, h1, skip, ln_g, ln_b, (float*)d_out);
}

// round 4
// speedup vs baseline: 1.8543x; 1.8543x over previous
#include <cuda_runtime.h>
#include <cuda_bf16.h>
#include <cstdint>
#include <math.h>

// ---------------------------------------------------------------------------
// Problem constants
// ---------------------------------------------------------------------------
#define NN 50000      // nodes per type
#define EE 200000     // edges per relation
// REL = [(0,1),(1,0),(0,0),(1,1)]
//   src type st = r&1 ; dst type dt = (r==0||r==3)
//   type 0 sources relations {0,2}; type 1 sources {1,3}
//   dst type 0 receives {1,2}; dst type 1 receives {0,3}
#define NC 640        // fused projection width: [K_rA | K_rB | V_rA | V_rB | Q]

// ---------------------------------------------------------------------------
// Scratch layout (floats)
// ---------------------------------------------------------------------------
constexpr size_t OFF_C0    = 0;                                  // NN*640
constexpr size_t OFF_C1    = OFF_C0    + (size_t)NN * NC;        // NN*640
constexpr size_t OFF_NUM   = OFF_C1    + (size_t)NN * NC;        // 4*NN*128
constexpr size_t OFF_DEN   = OFF_NUM   + (size_t)4 * NN * 128;   // 4*NN*8
constexpr size_t OFF_AGG   = OFF_DEN   + (size_t)4 * NN * 8;     // 2*NN*128
constexpr size_t OFF_TRANS = OFF_AGG   + (size_t)2 * NN * 128;   // 2*NN*128
constexpr size_t OFF_WCAT  = OFF_TRANS + (size_t)2 * NN * 128;   // 2*128*640
constexpr size_t OFF_BCAT  = OFF_WCAT  + (size_t)2 * 128 * NC;   // 2*640
constexpr size_t BUF_TOTAL = OFF_BCAT  + (size_t)2 * NC;

__device__ float g_buf[BUF_TOTAL];

// ---------------------------------------------------------------------------
// 3xTF32 helpers
// ---------------------------------------------------------------------------
__device__ __forceinline__ void split_tf32(float x, uint32_t& hi, uint32_t& lo) {
    asm("cvt.rna.tf32.f32 %0, %1;" : "=r"(hi) : "f"(x));
    float r = x - __uint_as_float(hi);
    asm("cvt.rna.tf32.f32 %0, %1;" : "=r"(lo) : "f"(r));
}

__device__ __forceinline__ void mma_tf32(float* c, const uint32_t* a, const uint32_t* b) {
    asm volatile(
        "mma.sync.aligned.m16n8k8.row.col.f32.tf32.tf32.f32 "
        "{%0,%1,%2,%3}, {%4,%5,%6,%7}, {%8,%9}, {%0,%1,%2,%3};"
        : "+f"(c[0]), "+f"(c[1]), "+f"(c[2]), "+f"(c[3])
        : "r"(a[0]), "r"(a[1]), "r"(a[2]), "r"(a[3]), "r"(b[0]), "r"(b[1]));
}

// ---------------------------------------------------------------------------
// Tensor-core GEMM (3xTF32): C[M, ldc] = A[M,128] @ W[128, ldw] + bias
// BM=128, BN=64, BK=32, 256 threads (8 warps as 4x2), warp tile 32x32.
// ---------------------------------------------------------------------------
#define BM 128
#define BN 64
#define BK 32

__global__ __launch_bounds__(256, 2) void gemm_tf32(const float* __restrict__ A,
                                                    const float* __restrict__ W, int ldw,
                                                    const float* __restrict__ bias,
                                                    float* __restrict__ C, int ldc,
                                                    int M) {
    __shared__ float As[BM][BK + 4];   // pad 4 -> conflict-free frag loads, float4-aligned
    __shared__ float Ws[BK][BN + 8];   // pad 8 -> conflict-free frag loads

    int tid  = threadIdx.x;
    int warp = tid >> 5;
    int lane = tid & 31;
    int g    = lane >> 2;   // group id 0..7
    int t4   = lane & 3;    // thread in group 0..3
    int warpM = warp >> 1;  // 0..3
    int warpN = warp & 1;   // 0..1

    int m0 = blockIdx.x * BM;
    int n0 = blockIdx.y * BN;

    float acc[2][4][4];
#pragma unroll
    for (int i = 0; i < 2; i++)
#pragma unroll
        for (int j = 0; j < 4; j++)
#pragma unroll
            for (int k = 0; k < 4; k++) acc[i][j][k] = 0.f;

    for (int kb = 0; kb < 128; kb += BK) {
        // ---- load A tile 128x32 (1024 float4, 4 per thread) ----
#pragma unroll
        for (int i = 0; i < 4; i++) {
            int f   = i * 256 + tid;    // 0..1023
            int row = f >> 3;           // 8 float4 per row
            int cg  = f & 7;
            int m   = m0 + row;
            float4 v = make_float4(0.f, 0.f, 0.f, 0.f);
            if (m < M) v = *(const float4*)&A[(size_t)m * 128 + kb + cg * 4];
            *(float4*)&As[row][cg * 4] = v;
        }
        // ---- load W tile 32x64 (512 float4, 2 per thread) ----
#pragma unroll
        for (int i = 0; i < 2; i++) {
            int f  = i * 256 + tid;     // 0..511
            int k  = f >> 4;            // 16 float4 per row
            int cg = f & 15;
            *(float4*)&Ws[k][cg * 4] =
                *(const float4*)&W[(size_t)(kb + k) * ldw + n0 + cg * 4];
        }
        __syncthreads();

#pragma unroll
        for (int ks = 0; ks < BK / 8; ks++) {
            int k0 = ks * 8;
            // A fragments (2 m-tiles)
            uint32_t ahi[2][4], alo[2][4];
#pragma unroll
            for (int mt = 0; mt < 2; mt++) {
                int rb = warpM * 32 + mt * 16;
                split_tf32(As[rb + g    ][k0 + t4    ], ahi[mt][0], alo[mt][0]);
                split_tf32(As[rb + g + 8][k0 + t4    ], ahi[mt][1], alo[mt][1]);
                split_tf32(As[rb + g    ][k0 + t4 + 4], ahi[mt][2], alo[mt][2]);
                split_tf32(As[rb + g + 8][k0 + t4 + 4], ahi[mt][3], alo[mt][3]);
            }
            // B fragments (4 n-tiles)
            uint32_t bhi[4][2], blo[4][2];
#pragma unroll
            for (int nt = 0; nt < 4; nt++) {
                int cb = warpN * 32 + nt * 8 + g;
                split_tf32(Ws[k0 + t4    ][cb], bhi[nt][0], blo[nt][0]);
                split_tf32(Ws[k0 + t4 + 4][cb], bhi[nt][1], blo[nt][1]);
            }
#pragma unroll
            for (int mt = 0; mt < 2; mt++)
#pragma unroll
                for (int nt = 0; nt < 4; nt++) {
                    mma_tf32(acc[mt][nt], ahi[mt], bhi[nt]);
                    mma_tf32(acc[mt][nt], ahi[mt], blo[nt]);
                    mma_tf32(acc[mt][nt], alo[mt], bhi[nt]);
                }
        }
        __syncthreads();
    }

    // ---- epilogue: bias + store ----
#pragma unroll
    for (int mt = 0; mt < 2; mt++) {
#pragma unroll
        for (int nt = 0; nt < 4; nt++) {
            int col = n0 + warpN * 32 + nt * 8 + t4 * 2;
            float b0 = bias[col], b1 = bias[col + 1];
            int r0 = m0 + warpM * 32 + mt * 16 + g;
            int r1 = r0 + 8;
            if (r0 < M) {
                float2 v = make_float2(acc[mt][nt][0] + b0, acc[mt][nt][1] + b1);
                *(float2*)&C[(size_t)r0 * ldc + col] = v;
            }
            if (r1 < M) {
                float2 v = make_float2(acc[mt][nt][2] + b0, acc[mt][nt][3] + b1);
                *(float2*)&C[(size_t)r1 * ldc + col] = v;
            }
        }
    }
}

// ---------------------------------------------------------------------------
// Build fused per-type weights WCAT[t][128][640] and biases BCAT[t][640]:
// cols [0,128)=K_rA, [128,256)=K_rB, [256,384)=V_rA, [384,512)=V_rB, [512,640)=Q
//   t=0: rA=0, rB=2 ;  t=1: rA=1, rB=3
// K/V slices fold rel_att / rel_msg: W[i][h*16+e] = sum_d Wsrc[i][h*16+d]*R[h][d][e]
// ---------------------------------------------------------------------------
__global__ void prep_wcat(const float* __restrict__ Wk, const float* __restrict__ bk,
                          const float* __restrict__ Wq, const float* __restrict__ bq,
                          const float* __restrict__ Wv, const float* __restrict__ bv,
                          const float* __restrict__ rel_att, const float* __restrict__ rel_msg) {
    int idx = blockIdx.x * blockDim.x + threadIdx.x;
    if (idx >= 2 * 128 * NC) return;
    int t = idx / (128 * NC);
    int i = (idx / NC) & 127;
    int c = idx % NC;

    float val, bval = 0.f;
    if (c < 512) {
        int sel = c >> 7;             // 0..3
        int rel = (sel & 1) ? (t == 0 ? 2 : 3) : (t == 0 ? 0 : 1);
        int isV = sel >> 1;
        int o = c & 127, h = o >> 4, eo = o & 15;
        const float* Wsrc = (isV ? Wv : Wk) + (size_t)t * 16384 + (size_t)i * 128 + h * 16;
        const float* bsrc = (isV ? bv : bk) + t * 128 + h * 16;
        const float* R = (isV ? rel_msg : rel_att) + (((size_t)rel * 8 + h) * 16) * 16 + eo;
        float a = 0.f, b = 0.f;
#pragma unroll
        for (int d = 0; d < 16; d++) {
            a += Wsrc[d] * R[d * 16];
            b += bsrc[d] * R[d * 16];
        }
        val = a; bval = b;
    } else {
        int o = c - 512;
        val = Wq[(size_t)t * 16384 + (size_t)i * 128 + o];
        bval = bq[t * 128 + o];
    }
    g_buf[OFF_WCAT + (size_t)t * 128 * NC + (size_t)i * NC + c] = val;
    if (i == 0) g_buf[OFF_BCAT + t * NC + c] = bval;
}

// ---------------------------------------------------------------------------
// Zero NUM and DEN
// ---------------------------------------------------------------------------
__global__ void zero_accum() {
    size_t n = (size_t)4 * NN * 128 + (size_t)4 * NN * 8;
    size_t i = (size_t)blockIdx.x * blockDim.x + threadIdx.x;
    size_t stride = (size_t)gridDim.x * blockDim.x;
    for (; i < n; i += stride) g_buf[OFF_NUM + i] = 0.f;
}

// ---------------------------------------------------------------------------
// Single edge pass: score -> exp -> den += ex -> num += ex * V[src]
// One warp per edge. Softmax max-shift is omitted (mathematically identical;
// scores are O(1) so exp() is fp32-safe).
// ---------------------------------------------------------------------------
__global__ void edge_pass(const float* __restrict__ pri,
                          const int* __restrict__ s0, const int* __restrict__ d0,
                          const int* __restrict__ s1, const int* __restrict__ d1,
                          const int* __restrict__ s2, const int* __restrict__ d2,
                          const int* __restrict__ s3, const int* __restrict__ d3) {
    int r = blockIdx.y;
    int e = blockIdx.x * (blockDim.x >> 5) + (threadIdx.x >> 5);
    if (e >= EE) return;
    int lane = threadIdx.x & 31;

    const int* src = (r == 0) ? s0 : (r == 1) ? s1 : (r == 2) ? s2 : s3;
    const int* dst = (r == 0) ? d0 : (r == 1) ? d1 : (r == 2) ? d2 : d3;
    int st = r & 1;
    int dt = (r == 0 || r == 3) ? 1 : 0;
    int sliceKV = (r >> 1) * 128;   // K at sliceKV, V at 256+sliceKV

    int s = src[e];
    int d = dst[e];

    const float* Cs = g_buf + (st ? OFF_C1 : OFF_C0) + (size_t)s * NC;
    const float* Cd = g_buf + (dt ? OFF_C1 : OFF_C0) + (size_t)d * NC;

    float4 q = *(const float4*)&Cd[512 + lane * 4];
    float4 k = *(const float4*)&Cs[sliceKV + lane * 4];
    float p = q.x * k.x + q.y * k.y + q.z * k.z + q.w * k.w;
    p += __shfl_xor_sync(0xffffffffu, p, 1);
    p += __shfl_xor_sync(0xffffffffu, p, 2);
    int h = lane >> 2;
    float sc = p * pri[r * 8 + h] * 0.25f;   // 1/sqrt(16)
    float ex = __expf(sc);

    if ((lane & 3) == 0) {
        float* dp = g_buf + OFF_DEN + ((size_t)r * NN + d) * 8 + h;
        asm volatile("red.global.add.f32 [%0], %1;" :: "l"(dp), "f"(ex) : "memory");
    }

    float4 v = *(const float4*)&Cs[256 + sliceKV + lane * 4];
    float* np = g_buf + OFF_NUM + ((size_t)r * NN + d) * 128 + lane * 4;
    asm volatile("red.global.add.v4.f32 [%0], {%1,%2,%3,%4};"
                 :: "l"(np), "f"(v.x * ex), "f"(v.y * ex), "f"(v.z * ex), "f"(v.w * ex)
                 : "memory");
}

// ---------------------------------------------------------------------------
// Node-level normalization + cross-relation mean -> AGG
// ---------------------------------------------------------------------------
__global__ void agg_kernel() {
    size_t total = (size_t)2 * NN * 128;
    size_t i = (size_t)blockIdx.x * blockDim.x + threadIdx.x;
    size_t stride = (size_t)gridDim.x * blockDim.x;
    for (; i < total; i += stride) {
        int j = (int)(i & 127);
        size_t nt = i >> 7;
        int t = (int)(nt / NN);
        int n = (int)(nt % NN);
        int rA = (t == 0) ? 1 : 0;   // relations targeting type t
        int rB = (t == 0) ? 2 : 3;
        int h = j >> 4;
        float a = 0.f;
        float dA = g_buf[OFF_DEN + ((size_t)rA * NN + n) * 8 + h];
        if (dA > 0.f) a += g_buf[OFF_NUM + ((size_t)rA * NN + n) * 128 + j] / dA;
        float dB = g_buf[OFF_DEN + ((size_t)rB * NN + n) * 8 + h];
        if (dB > 0.f) a += g_buf[OFF_NUM + ((size_t)rB * NN + n) * 128 + j] / dB;
        g_buf[OFF_AGG + i] = 0.5f * a;
    }
}

// ---------------------------------------------------------------------------
// Skip + LayerNorm. One warp per row.
// ---------------------------------------------------------------------------
__global__ void ln_kernel(const float* __restrict__ h0, const float* __restrict__ h1,
                          const float* __restrict__ skip,
                          const float* __restrict__ ln_g, const float* __restrict__ ln_b,
                          float* __restrict__ out) {
    int warp = (blockIdx.x * blockDim.x + threadIdx.x) >> 5;
    int lane = threadIdx.x & 31;
    if (warp >= 2 * NN) return;
    int t = warp / NN;
    int n = warp % NN;

    const float* hh = (t == 0) ? h0 : h1;
    const float* tr = g_buf + OFF_TRANS + ((size_t)t * NN + n) * 128;
    float alpha = 1.f / (1.f + __expf(-skip[t]));
    float beta = 1.f - alpha;

    float4 tv = *(const float4*)&tr[lane * 4];
    float4 hv = *(const float4*)&hh[(size_t)n * 128 + lane * 4];
    float4 x;
    x.x = tv.x * alpha + hv.x * beta;
    x.y = tv.y * alpha + hv.y * beta;
    x.z = tv.z * alpha + hv.z * beta;
    x.w = tv.w * alpha + hv.w * beta;

    float s1 = x.x + x.y + x.z + x.w;
    float s2 = x.x * x.x + x.y * x.y + x.z * x.z + x.w * x.w;
#pragma unroll
    for (int o = 16; o >= 1; o >>= 1) {
        s1 += __shfl_xor_sync(0xffffffffu, s1, o);
        s2 += __shfl_xor_sync(0xffffffffu, s2, o);
    }
    float mean = s1 * (1.f / 128.f);
    float var  = s2 * (1.f / 128.f) - mean * mean;
    float rstd = rsqrtf(var + 1e-5f);

    int j = lane * 4;
    float4 g4 = *(const float4*)&ln_g[t * 128 + j];
    float4 b4 = *(const float4*)&ln_b[t * 128 + j];
    float4 o4;
    o4.x = (x.x - mean) * rstd * g4.x + b4.x;
    o4.y = (x.y - mean) * rstd * g4.y + b4.y;
    o4.z = (x.z - mean) * rstd * g4.z + b4.z;
    o4.w = (x.w - mean) * rstd * g4.w + b4.w;
    *(float4*)&out[((size_t)t * NN + n) * 128 + j] = o4;
}

// ---------------------------------------------------------------------------
// Host launcher
// ---------------------------------------------------------------------------
extern "C" void kernel_launch(void* const* d_in, const int* in_sizes, int n_in,
                              void* d_out, int out_size) {
    const float* h0 = (const float*)d_in[0];
    const float* h1 = (const float*)d_in[1];
    const int* s0 = (const int*)d_in[2];
    const int* d0 = (const int*)d_in[3];
    const int* s1 = (const int*)d_in[4];
    const int* d1 = (const int*)d_in[5];
    const int* s2 = (const int*)d_in[6];
    const int* d2 = (const int*)d_in[7];
    const int* s3 = (const int*)d_in[8];
    const int* d3 = (const int*)d_in[9];
    const float* Wk = (const float*)d_in[10];
    const float* bk = (const float*)d_in[11];
    const float* Wq = (const float*)d_in[12];
    const float* bq = (const float*)d_in[13];
    const float* Wv = (const float*)d_in[14];
    const float* bv = (const float*)d_in[15];
    const float* Wa = (const float*)d_in[16];
    const float* ba = (const float*)d_in[17];
    const float* rel_att = (const float*)d_in[18];
    const float* rel_msg = (const float*)d_in[19];
    const float* rel_pri = (const float*)d_in[20];
    const float* skip = (const float*)d_in[21];
    const float* ln_g = (const float*)d_in[22];
    const float* ln_b = (const float*)d_in[23];

    static float* buf = nullptr;
    if (!buf) cudaGetSymbolAddress((void**)&buf, g_buf);

    // 1) fused weights + zero accumulators
    prep_wcat<<<(2 * 128 * NC + 255) / 256, 256>>>(Wk, bk, Wq, bq, Wv, bv, rel_att, rel_msg);
    zero_accum<<<2048, 256>>>();

    // 2) fused KVQ projections: per type, [NN,128] x [128,640]
    int mblocks = (NN + BM - 1) / BM;
    const float* hs[2] = {h0, h1};
    for (int t = 0; t < 2; t++) {
        dim3 gg(mblocks, NC / BN);
        gemm_tf32<<<gg, 256>>>(hs[t], buf + OFF_WCAT + (size_t)t * 128 * NC, NC,
                               buf + OFF_BCAT + t * NC,
                               buf + (t ? OFF_C1 : OFF_C0), NC, NN);
    }

    // 3) single edge pass (scores + softmax accumulation)
    dim3 gE((EE + 7) / 8, 4);
    edge_pass<<<gE, 256>>>(rel_pri, s0, d0, s1, d1, s2, d2, s3, d3);

    // 4) normalize + cross-relation mean
    agg_kernel<<<2048, 256>>>();

    // 5) output projection [NN,128] x [128,128] per type
    for (int t = 0; t < 2; t++) {
        dim3 gg(mblocks, 128 / BN);
        gemm_tf32<<<gg, 256>>>(buf + OFF_AGG + (size_t)t * NN * 128,
                               Wa + (size_t)t * 16384, 128,
                               ba + t * 128,
                               buf + OFF_TRANS + (size_t)t * NN * 128, 128, NN);
    }

    // 6) skip + layernorm -> out
    ln_kernel<<<(2 * NN * 32 + 255) / 256, 256>>>(h0, h1, skip, ln_g, ln_b, (float*)d_out);
}

// round 5
// speedup vs baseline: 2.1981x; 1.1854x over previous
#include <cuda_runtime.h>
#include <cuda_bf16.h>
#include <cstdint>
#include <math.h>

// ---------------------------------------------------------------------------
// Problem constants
// ---------------------------------------------------------------------------
#define NN 50000      // nodes per type
#define EE 200000     // edges per relation
// REL = [(0,1),(1,0),(0,0),(1,1)]
//   src type st = r&1 ; dst type dt = (r==0||r==3)
//   type 0 sources relations {0,2}; type 1 sources {1,3}
//   dst type 0 receives {1,2}; dst type 1 receives {0,3}
#define NC 640        // fused projection width: [K_rA | K_rB | V_rA | V_rB | Q]

// ---------------------------------------------------------------------------
// Scratch layout (floats / 32-bit words)
// ---------------------------------------------------------------------------
constexpr size_t OFF_C0    = 0;                                  // NN*640
constexpr size_t OFF_C1    = OFF_C0    + (size_t)NN * NC;        // NN*640
constexpr size_t OFF_NUM   = OFF_C1    + (size_t)NN * NC;        // 4*NN*128
constexpr size_t OFF_DEN   = OFF_NUM   + (size_t)4 * NN * 128;   // 4*NN*8
constexpr size_t OFF_AGG   = OFF_DEN   + (size_t)4 * NN * 8;     // 2*NN*128
constexpr size_t OFF_TRANS = OFF_AGG   + (size_t)2 * NN * 128;   // 2*NN*128
constexpr size_t OFF_WCAT  = OFF_TRANS + (size_t)2 * NN * 128;   // 2*128*640 (fp32)
constexpr size_t OFF_BCAT  = OFF_WCAT  + (size_t)2 * 128 * NC;   // 2*640
// packed bf16x2 weight images (uint32 words): [t][K/2][cols]
constexpr size_t OFF_WH    = OFF_BCAT  + (size_t)2 * NC;         // 2*64*640
constexpr size_t OFF_WL    = OFF_WH    + (size_t)2 * 64 * NC;    // 2*64*640
constexpr size_t OFF_WAH   = OFF_WL    + (size_t)2 * 64 * NC;    // 2*64*128
constexpr size_t OFF_WAL   = OFF_WAH   + (size_t)2 * 64 * 128;   // 2*64*128
constexpr size_t BUF_TOTAL = OFF_WAL   + (size_t)2 * 64 * 128;

__device__ float g_buf[BUF_TOTAL];

// ---------------------------------------------------------------------------
// bf16 helpers
// ---------------------------------------------------------------------------
// pack {lo=x, hi=y} as bf16x2 (rn)
__device__ __forceinline__ uint32_t pack_bf16x2(float x, float y) {
    uint32_t r;
    asm("cvt.rn.bf16x2.f32 %0, %1, %2;" : "=r"(r) : "f"(y), "f"(x));
    return r;
}
__device__ __forceinline__ float lo_as_f32(uint32_t p) { return __uint_as_float(p << 16); }
__device__ __forceinline__ float hi_as_f32(uint32_t p) { return __uint_as_float(p & 0xffff0000u); }

__device__ __forceinline__ void mma_bf16(float* c, const uint32_t* a, const uint32_t* b) {
    asm volatile(
        "mma.sync.aligned.m16n8k16.row.col.f32.bf16.bf16.f32 "
        "{%0,%1,%2,%3}, {%4,%5,%6,%7}, {%8,%9}, {%0,%1,%2,%3};"
        : "+f"(c[0]), "+f"(c[1]), "+f"(c[2]), "+f"(c[3])
        : "r"(a[0]), "r"(a[1]), "r"(a[2]), "r"(a[3]), "r"(b[0]), "r"(b[1]));
}

// ---------------------------------------------------------------------------
// 3xBF16 tensor-core GEMM: C[M, ldc] = A[M,128] @ W[128, ldw] + bias
// A fp32 (split to bf16 hi/lo at smem-load time, packed along K).
// W pre-split into packed hi/lo images (WH/WL, uint32 [K/2][ldw]).
// BM=128, BN=64, BK=32, 256 threads (8 warps 4x2), warp tile 32x32.
// ---------------------------------------------------------------------------
#define BM 128
#define BN 64
#define BK 32

__global__ __launch_bounds__(256, 2) void gemm_bf16(const float* __restrict__ A,
                                                    const uint32_t* __restrict__ WH,
                                                    const uint32_t* __restrict__ WL,
                                                    int ldw,
                                                    const float* __restrict__ bias,
                                                    float* __restrict__ C, int ldc,
                                                    int M) {
    __shared__ uint32_t AsH[BM][17], AsL[BM][17];     // 16 packed-K cols + 1 pad
    __shared__ uint32_t WsH[16][BN + 4], WsL[16][BN + 4];

    int tid  = threadIdx.x;
    int warp = tid >> 5;
    int lane = tid & 31;
    int g    = lane >> 2;   // group id 0..7
    int t4   = lane & 3;    // thread in group 0..3
    int warpM = warp >> 1;  // 0..3
    int warpN = warp & 1;   // 0..1

    int m0 = blockIdx.x * BM;
    int n0 = blockIdx.y * BN;

    float acc[2][4][4];
#pragma unroll
    for (int i = 0; i < 2; i++)
#pragma unroll
        for (int j = 0; j < 4; j++)
#pragma unroll
            for (int k = 0; k < 4; k++) acc[i][j][k] = 0.f;

    for (int kb = 0; kb < 128; kb += BK) {
        int kb2 = kb >> 1;   // packed row base in W images
        // ---- A tile 128x32 floats = 1024 float4; 4 per thread; split+pack ----
#pragma unroll
        for (int i = 0; i < 4; i++) {
            int f   = i * 256 + tid;
            int row = f >> 3;           // 8 float4 per row
            int cg  = f & 7;            // float4 index within row
            int m   = m0 + row;
            float4 v = make_float4(0.f, 0.f, 0.f, 0.f);
            if (m < M) v = *(const float4*)&A[(size_t)m * 128 + kb + cg * 4];
            uint32_t h0 = pack_bf16x2(v.x, v.y);
            uint32_t h1 = pack_bf16x2(v.z, v.w);
            uint32_t l0 = pack_bf16x2(v.x - lo_as_f32(h0), v.y - hi_as_f32(h0));
            uint32_t l1 = pack_bf16x2(v.z - lo_as_f32(h1), v.w - hi_as_f32(h1));
            AsH[row][cg * 2]     = h0;
            AsH[row][cg * 2 + 1] = h1;
            AsL[row][cg * 2]     = l0;
            AsL[row][cg * 2 + 1] = l1;
        }
        // ---- W tile: 16 packed rows x 64 cols = 256 uint4; 1 per thread ----
        {
            int pk = tid >> 4;          // 0..15
            int cg = tid & 15;          // 16 uint4 per row
            *(uint4*)&WsH[pk][cg * 4] = *(const uint4*)&WH[(size_t)(kb2 + pk) * ldw + n0 + cg * 4];
            *(uint4*)&WsL[pk][cg * 4] = *(const uint4*)&WL[(size_t)(kb2 + pk) * ldw + n0 + cg * 4];
        }
        __syncthreads();

#pragma unroll
        for (int ks = 0; ks < 2; ks++) {   // two k16 steps per BK=32
            int kp = ks * 8;               // packed col base
            uint32_t ah[2][4], al[2][4];
#pragma unroll
            for (int mt = 0; mt < 2; mt++) {
                int rb = warpM * 32 + mt * 16;
                ah[mt][0] = AsH[rb + g    ][kp + t4];
                ah[mt][1] = AsH[rb + g + 8][kp + t4];
                ah[mt][2] = AsH[rb + g    ][kp + t4 + 4];
                ah[mt][3] = AsH[rb + g + 8][kp + t4 + 4];
                al[mt][0] = AsL[rb + g    ][kp + t4];
                al[mt][1] = AsL[rb + g + 8][kp + t4];
                al[mt][2] = AsL[rb + g    ][kp + t4 + 4];
                al[mt][3] = AsL[rb + g + 8][kp + t4 + 4];
            }
            uint32_t bh[4][2], bl[4][2];
#pragma unroll
            for (int nt = 0; nt < 4; nt++) {
                int cb = warpN * 32 + nt * 8 + g;
                bh[nt][0] = WsH[kp + t4    ][cb];
                bh[nt][1] = WsH[kp + t4 + 4][cb];
                bl[nt][0] = WsL[kp + t4    ][cb];
                bl[nt][1] = WsL[kp + t4 + 4][cb];
            }
#pragma unroll
            for (int mt = 0; mt < 2; mt++)
#pragma unroll
                for (int nt = 0; nt < 4; nt++) {
                    mma_bf16(acc[mt][nt], ah[mt], bh[nt]);
                    mma_bf16(acc[mt][nt], ah[mt], bl[nt]);
                    mma_bf16(acc[mt][nt], al[mt], bh[nt]);
                }
        }
        __syncthreads();
    }

    // ---- epilogue: bias + store (c layout identical to tf32 m16n8k8) ----
#pragma unroll
    for (int mt = 0; mt < 2; mt++) {
#pragma unroll
        for (int nt = 0; nt < 4; nt++) {
            int col = n0 + warpN * 32 + nt * 8 + t4 * 2;
            float b0 = bias[col], b1 = bias[col + 1];
            int r0 = m0 + warpM * 32 + mt * 16 + g;
            int r1 = r0 + 8;
            if (r0 < M) {
                float2 v = make_float2(acc[mt][nt][0] + b0, acc[mt][nt][1] + b1);
                *(float2*)&C[(size_t)r0 * ldc + col] = v;
            }
            if (r1 < M) {
                float2 v = make_float2(acc[mt][nt][2] + b0, acc[mt][nt][3] + b1);
                *(float2*)&C[(size_t)r1 * ldc + col] = v;
            }
        }
    }
}

// ---------------------------------------------------------------------------
// Build fused per-type fp32 weights WCAT[t][128][640] and biases BCAT[t][640]:
// cols [0,128)=K_rA, [128,256)=K_rB, [256,384)=V_rA, [384,512)=V_rB, [512,640)=Q
//   t=0: rA=0, rB=2 ;  t=1: rA=1, rB=3
// ---------------------------------------------------------------------------
__global__ void prep_wcat(const float* __restrict__ Wk, const float* __restrict__ bk,
                          const float* __restrict__ Wq, const float* __restrict__ bq,
                          const float* __restrict__ Wv, const float* __restrict__ bv,
                          const float* __restrict__ rel_att, const float* __restrict__ rel_msg) {
    int idx = blockIdx.x * blockDim.x + threadIdx.x;
    if (idx >= 2 * 128 * NC) return;
    int t = idx / (128 * NC);
    int i = (idx / NC) & 127;
    int c = idx % NC;

    float val, bval = 0.f;
    if (c < 512) {
        int sel = c >> 7;             // 0..3
        int rel = (sel & 1) ? (t == 0 ? 2 : 3) : (t == 0 ? 0 : 1);
        int isV = sel >> 1;
        int o = c & 127, h = o >> 4, eo = o & 15;
        const float* Wsrc = (isV ? Wv : Wk) + (size_t)t * 16384 + (size_t)i * 128 + h * 16;
        const float* bsrc = (isV ? bv : bk) + t * 128 + h * 16;
        const float* R = (isV ? rel_msg : rel_att) + (((size_t)rel * 8 + h) * 16) * 16 + eo;
        float a = 0.f, b = 0.f;
#pragma unroll
        for (int d = 0; d < 16; d++) {
            a += Wsrc[d] * R[d * 16];
            b += bsrc[d] * R[d * 16];
        }
        val = a; bval = b;
    } else {
        int o = c - 512;
        val = Wq[(size_t)t * 16384 + (size_t)i * 128 + o];
        bval = bq[t * 128 + o];
    }
    g_buf[OFF_WCAT + (size_t)t * 128 * NC + (size_t)i * NC + c] = val;
    if (i == 0) g_buf[OFF_BCAT + t * NC + c] = bval;
}

// ---------------------------------------------------------------------------
// Pack fp32 weights into bf16 hi/lo images, packed pairs along K.
//  WCAT [t][128][640] -> WH/WL [t][64][640]
//  Wa   [t][128][128] -> WAH/WAL [t][64][128]
// ---------------------------------------------------------------------------
__global__ void pack_weights(const float* __restrict__ Wa) {
    uint32_t* W32 = (uint32_t*)g_buf;
    int idx = blockIdx.x * blockDim.x + threadIdx.x;
    int n_cat = 2 * 64 * NC;
    int n_wa  = 2 * 64 * 128;
    if (idx < n_cat) {
        int t  = idx / (64 * NC);
        int pk = (idx / NC) & 63;
        int n  = idx % NC;
        const float* Wt = g_buf + OFF_WCAT + (size_t)t * 128 * NC;
        float w0 = Wt[(size_t)(2 * pk)     * NC + n];
        float w1 = Wt[(size_t)(2 * pk + 1) * NC + n];
        uint32_t h = pack_bf16x2(w0, w1);
        uint32_t l = pack_bf16x2(w0 - lo_as_f32(h), w1 - hi_as_f32(h));
        W32[OFF_WH + (size_t)t * 64 * NC + (size_t)pk * NC + n] = h;
        W32[OFF_WL + (size_t)t * 64 * NC + (size_t)pk * NC + n] = l;
    } else if (idx < n_cat + n_wa) {
        int j  = idx - n_cat;
        int t  = j / (64 * 128);
        int pk = (j / 128) & 63;
        int n  = j % 128;
        float w0 = Wa[(size_t)t * 16384 + (size_t)(2 * pk)     * 128 + n];
        float w1 = Wa[(size_t)t * 16384 + (size_t)(2 * pk + 1) * 128 + n];
        uint32_t h = pack_bf16x2(w0, w1);
        uint32_t l = pack_bf16x2(w0 - lo_as_f32(h), w1 - hi_as_f32(h));
        W32[OFF_WAH + (size_t)t * 64 * 128 + (size_t)pk * 128 + n] = h;
        W32[OFF_WAL + (size_t)t * 64 * 128 + (size_t)pk * 128 + n] = l;
    }
}

// ---------------------------------------------------------------------------
// Zero NUM and DEN
// ---------------------------------------------------------------------------
__global__ void zero_accum() {
    size_t n = (size_t)4 * NN * 128 + (size_t)4 * NN * 8;
    size_t i = (size_t)blockIdx.x * blockDim.x + threadIdx.x;
    size_t stride = (size_t)gridDim.x * blockDim.x;
    for (; i < n; i += stride) g_buf[OFF_NUM + i] = 0.f;
}

// ---------------------------------------------------------------------------
// Single edge pass: score -> exp -> den += ex -> num += ex * V[src]
// One warp per edge. Softmax max-shift omitted (mathematically identical;
// scores are O(1) so exp() is fp32-safe).
// ---------------------------------------------------------------------------
__global__ void edge_pass(const float* __restrict__ pri,
                          const int* __restrict__ s0, const int* __restrict__ d0,
                          const int* __restrict__ s1, const int* __restrict__ d1,
                          const int* __restrict__ s2, const int* __restrict__ d2,
                          const int* __restrict__ s3, const int* __restrict__ d3) {
    int r = blockIdx.y;
    int e = blockIdx.x * (blockDim.x >> 5) + (threadIdx.x >> 5);
    if (e >= EE) return;
    int lane = threadIdx.x & 31;

    const int* src = (r == 0) ? s0 : (r == 1) ? s1 : (r == 2) ? s2 : s3;
    const int* dst = (r == 0) ? d0 : (r == 1) ? d1 : (r == 2) ? d2 : d3;
    int st = r & 1;
    int dt = (r == 0 || r == 3) ? 1 : 0;
    int sliceKV = (r >> 1) * 128;   // K at sliceKV, V at 256+sliceKV

    int s = src[e];
    int d = dst[e];

    const float* Cs = g_buf + (st ? OFF_C1 : OFF_C0) + (size_t)s * NC;
    const float* Cd = g_buf + (dt ? OFF_C1 : OFF_C0) + (size_t)d * NC;

    float4 q = *(const float4*)&Cd[512 + lane * 4];
    float4 k = *(const float4*)&Cs[sliceKV + lane * 4];
    float p = q.x * k.x + q.y * k.y + q.z * k.z + q.w * k.w;
    p += __shfl_xor_sync(0xffffffffu, p, 1);
    p += __shfl_xor_sync(0xffffffffu, p, 2);
    int h = lane >> 2;
    float sc = p * pri[r * 8 + h] * 0.25f;   // 1/sqrt(16)
    float ex = __expf(sc);

    if ((lane & 3) == 0) {
        float* dp = g_buf + OFF_DEN + ((size_t)r * NN + d) * 8 + h;
        asm volatile("red.global.add.f32 [%0], %1;" :: "l"(dp), "f"(ex) : "memory");
    }

    float4 v = *(const float4*)&Cs[256 + sliceKV + lane * 4];
    float* np = g_buf + OFF_NUM + ((size_t)r * NN + d) * 128 + lane * 4;
    asm volatile("red.global.add.v4.f32 [%0], {%1,%2,%3,%4};"
                 :: "l"(np), "f"(v.x * ex), "f"(v.y * ex), "f"(v.z * ex), "f"(v.w * ex)
                 : "memory");
}

// ---------------------------------------------------------------------------
// Node-level normalization + cross-relation mean -> AGG
// ---------------------------------------------------------------------------
__global__ void agg_kernel() {
    size_t total = (size_t)2 * NN * 128;
    size_t i = (size_t)blockIdx.x * blockDim.x + threadIdx.x;
    size_t stride = (size_t)gridDim.x * blockDim.x;
    for (; i < total; i += stride) {
        int j = (int)(i & 127);
        size_t nt = i >> 7;
        int t = (int)(nt / NN);
        int n = (int)(nt % NN);
        int rA = (t == 0) ? 1 : 0;   // relations targeting type t
        int rB = (t == 0) ? 2 : 3;
        int h = j >> 4;
        float a = 0.f;
        float dA = g_buf[OFF_DEN + ((size_t)rA * NN + n) * 8 + h];
        if (dA > 0.f) a += g_buf[OFF_NUM + ((size_t)rA * NN + n) * 128 + j] / dA;
        float dB = g_buf[OFF_DEN + ((size_t)rB * NN + n) * 8 + h];
        if (dB > 0.f) a += g_buf[OFF_NUM + ((size_t)rB * NN + n) * 128 + j] / dB;
        g_buf[OFF_AGG + i] = 0.5f * a;
    }
}

// ---------------------------------------------------------------------------
// Skip + LayerNorm. One warp per row.
// ---------------------------------------------------------------------------
__global__ void ln_kernel(const float* __restrict__ h0, const float* __restrict__ h1,
                          const float* __restrict__ skip,
                          const float* __restrict__ ln_g, const float* __restrict__ ln_b,
                          float* __restrict__ out) {
    int warp = (blockIdx.x * blockDim.x + threadIdx.x) >> 5;
    int lane = threadIdx.x & 31;
    if (warp >= 2 * NN) return;
    int t = warp / NN;
    int n = warp % NN;

    const float* hh = (t == 0) ? h0 : h1;
    const float* tr = g_buf + OFF_TRANS + ((size_t)t * NN + n) * 128;
    float alpha = 1.f / (1.f + __expf(-skip[t]));
    float beta = 1.f - alpha;

    float4 tv = *(const float4*)&tr[lane * 4];
    float4 hv = *(const float4*)&hh[(size_t)n * 128 + lane * 4];
    float4 x;
    x.x = tv.x * alpha + hv.x * beta;
    x.y = tv.y * alpha + hv.y * beta;
    x.z = tv.z * alpha + hv.z * beta;
    x.w = tv.w * alpha + hv.w * beta;

    float s1 = x.x + x.y + x.z + x.w;
    float s2 = x.x * x.x + x.y * x.y + x.z * x.z + x.w * x.w;
#pragma unroll
    for (int o = 16; o >= 1; o >>= 1) {
        s1 += __shfl_xor_sync(0xffffffffu, s1, o);
        s2 += __shfl_xor_sync(0xffffffffu, s2, o);
    }
    float mean = s1 * (1.f / 128.f);
    float var  = s2 * (1.f / 128.f) - mean * mean;
    float rstd = rsqrtf(var + 1e-5f);

    int j = lane * 4;
    float4 g4 = *(const float4*)&ln_g[t * 128 + j];
    float4 b4 = *(const float4*)&ln_b[t * 128 + j];
    float4 o4;
    o4.x = (x.x - mean) * rstd * g4.x + b4.x;
    o4.y = (x.y - mean) * rstd * g4.y + b4.y;
    o4.z = (x.z - mean) * rstd * g4.z + b4.z;
    o4.w = (x.w - mean) * rstd * g4.w + b4.w;
    *(float4*)&out[((size_t)t * NN + n) * 128 + j] = o4;
}

// ---------------------------------------------------------------------------
// Host launcher
// ---------------------------------------------------------------------------
extern "C" void kernel_launch(void* const* d_in, const int* in_sizes, int n_in,
                              void* d_out, int out_size) {
    const float* h0 = (const float*)d_in[0];
    const float* h1 = (const float*)d_in[1];
    const int* s0 = (const int*)d_in[2];
    const int* d0 = (const int*)d_in[3];
    const int* s1 = (const int*)d_in[4];
    const int* d1 = (const int*)d_in[5];
    const int* s2 = (const int*)d_in[6];
    const int* d2 = (const int*)d_in[7];
    const int* s3 = (const int*)d_in[8];
    const int* d3 = (const int*)d_in[9];
    const float* Wk = (const float*)d_in[10];
    const float* bk = (const float*)d_in[11];
    const float* Wq = (const float*)d_in[12];
    const float* bq = (const float*)d_in[13];
    const float* Wv = (const float*)d_in[14];
    const float* bv = (const float*)d_in[15];
    const float* Wa = (const float*)d_in[16];
    const float* ba = (const float*)d_in[17];
    const float* rel_att = (const float*)d_in[18];
    const float* rel_msg = (const float*)d_in[19];
    const float* rel_pri = (const float*)d_in[20];
    const float* skip = (const float*)d_in[21];
    const float* ln_g = (const float*)d_in[22];
    const float* ln_b = (const float*)d_in[23];

    static float* buf = nullptr;
    if (!buf) cudaGetSymbolAddress((void**)&buf, g_buf);
    uint32_t* buf32 = (uint32_t*)buf;

    // 1) fused fp32 weights, then pack to bf16 hi/lo; zero accumulators
    prep_wcat<<<(2 * 128 * NC + 255) / 256, 256>>>(Wk, bk, Wq, bq, Wv, bv, rel_att, rel_msg);
    pack_weights<<<(2 * 64 * NC + 2 * 64 * 128 + 255) / 256, 256>>>(Wa);
    zero_accum<<<2048, 256>>>();

    // 2) fused KVQ projections: per type, [NN,128] x [128,640]
    int mblocks = (NN + BM - 1) / BM;
    const float* hs[2] = {h0, h1};
    for (int t = 0; t < 2; t++) {
        dim3 gg(mblocks, NC / BN);
        gemm_bf16<<<gg, 256>>>(hs[t],
                               buf32 + OFF_WH + (size_t)t * 64 * NC,
                               buf32 + OFF_WL + (size_t)t * 64 * NC, NC,
                               buf + OFF_BCAT + t * NC,
                               buf + (t ? OFF_C1 : OFF_C0), NC, NN);
    }

    // 3) single edge pass (scores + softmax accumulation)
    dim3 gE((EE + 7) / 8, 4);
    edge_pass<<<gE, 256>>>(rel_pri, s0, d0, s1, d1, s2, d2, s3, d3);

    // 4) normalize + cross-relation mean
    agg_kernel<<<2048, 256>>>();

    // 5) output projection [NN,128] x [128,128] per type
    for (int t = 0; t < 2; t++) {
        dim3 gg(mblocks, 128 / BN);
        gemm_bf16<<<gg, 256>>>(buf + OFF_AGG + (size_t)t * NN * 128,
                               buf32 + OFF_WAH + (size_t)t * 64 * 128,
                               buf32 + OFF_WAL + (size_t)t * 64 * 128, 128,
                               ba + t * 128,
                               buf + OFF_TRANS + (size_t)t * NN * 128, 128, NN);
    }

    // 6) skip + layernorm -> out
    ln_kernel<<<(2 * NN * 32 + 255) / 256, 256>>>(h0, h1, skip, ln_g, ln_b, (float*)d_out);
}

// round 7
// speedup vs baseline: 2.3770x; 1.0814x over previous
#include <cuda_runtime.h>
#include <cuda_bf16.h>
#include <cstdint>
#include <math.h>

// ---------------------------------------------------------------------------
// Problem constants
// ---------------------------------------------------------------------------
#define NN 50000      // nodes per type
#define EE 200000     // edges per relation
// REL = [(0,1),(1,0),(0,0),(1,1)]
//   src type st = r&1 ; dst type dt = (r==0||r==3)
//   dst type 0 receives {1,2}; dst type 1 receives {0,3}
#define NC 640        // fused projection width: [K_rA | K_rB | V_rA | V_rB | Q]
#define NCW 320       // bf16-packed row width in 32-bit words

// ---------------------------------------------------------------------------
// Scratch layout (32-bit words)
// ---------------------------------------------------------------------------
constexpr size_t OFF_C0    = 0;                                  // NN*320 (bf16x2)
constexpr size_t OFF_C1    = OFF_C0    + (size_t)NN * NCW;       // NN*320 (bf16x2)
constexpr size_t OFF_NUM   = OFF_C1    + (size_t)NN * NCW;       // 4*NN*128 fp32
constexpr size_t OFF_DEN   = OFF_NUM   + (size_t)4 * NN * 128;   // 4*NN*8 fp32
constexpr size_t OFF_AGG   = OFF_DEN   + (size_t)4 * NN * 8;     // 2*NN*128 fp32
constexpr size_t OFF_TRANS = OFF_AGG   + (size_t)2 * NN * 128;   // 2*NN*128 fp32
constexpr size_t OFF_WCAT  = OFF_TRANS + (size_t)2 * NN * 128;   // 2*128*640 fp32
constexpr size_t OFF_BCAT  = OFF_WCAT  + (size_t)2 * 128 * NC;   // 2*640 fp32
// packed bf16x2 weight images (uint32): [t][K/2][cols], cols PERMUTED in 64-groups
constexpr size_t OFF_WH    = OFF_BCAT  + (size_t)2 * NC;         // 2*64*640
constexpr size_t OFF_WL    = OFF_WH    + (size_t)2 * 64 * NC;    // 2*64*640
constexpr size_t OFF_WAH   = OFF_WL    + (size_t)2 * 64 * NC;    // 2*64*128
constexpr size_t OFF_WAL   = OFF_WAH   + (size_t)2 * 64 * 128;   // 2*64*128
constexpr size_t BUF_TOTAL = OFF_WAL   + (size_t)2 * 64 * 128;

__device__ float g_buf[BUF_TOTAL];

// ---------------------------------------------------------------------------
// helpers
// ---------------------------------------------------------------------------
__device__ __forceinline__ uint32_t pack_bf16x2(float x, float y) {
    uint32_t r;
    asm("cvt.rn.bf16x2.f32 %0, %1, %2;" : "=r"(r) : "f"(y), "f"(x));
    return r;
}
__device__ __forceinline__ float lo_as_f32(uint32_t p) { return __uint_as_float(p << 16); }
__device__ __forceinline__ float hi_as_f32(uint32_t p) { return __uint_as_float(p & 0xffff0000u); }

__device__ __forceinline__ void mma_bf16(float* c, const uint32_t* a, const uint32_t* b) {
    asm volatile(
        "mma.sync.aligned.m16n8k16.row.col.f32.bf16.bf16.f32 "
        "{%0,%1,%2,%3}, {%4,%5,%6,%7}, {%8,%9}, {%0,%1,%2,%3};"
        : "+f"(c[0]), "+f"(c[1]), "+f"(c[2]), "+f"(c[3])
        : "r"(a[0]), "r"(a[1]), "r"(a[2]), "r"(a[3]), "r"(b[0]), "r"(b[1]));
}

__device__ __forceinline__ void ldsm_x4(uint32_t* r, uint32_t addr) {
    asm volatile("ldmatrix.sync.aligned.m8n8.x4.shared.b16 {%0,%1,%2,%3}, [%4];"
                 : "=r"(r[0]), "=r"(r[1]), "=r"(r[2]), "=r"(r[3]) : "r"(addr));
}

// column permutation within each 64-col group (word-granular; packing is along K)
__host__ __device__ __forceinline__ int wperm(int n) {
    return (n & ~63) | (((n & 7) << 3) | ((n >> 3) & 7));
}

// ---------------------------------------------------------------------------
// 3xBF16 tensor-core GEMM: C[M, *] = A[M,128] @ W[128, ldw] + bias
// A fp32 (split to packed bf16 hi/lo at smem-load); W pre-split + pre-permuted.
// BM=128, BN=64, BK=32, 256 threads (8 warps 4x2), warp tile 32x32.
// A smem pitch = 20 words (80B): 16B-aligned rows for ldmatrix AND
// conflict-free row-start rotation ((20*r) mod 32 distinct per 8-row phase).
// ---------------------------------------------------------------------------
#define BM 128
#define BN 64
#define BK 32
#define APITCH 20

template<bool OUT_BF16>
__global__ __launch_bounds__(256, 2) void gemm3(const float* __restrict__ A,
                                                const uint32_t* __restrict__ WH,
                                                const uint32_t* __restrict__ WL,
                                                int ldww,
                                                const float* __restrict__ bias,
                                                uint32_t* __restrict__ Cw, int ldcw,
                                                int M) {
    __shared__ uint32_t AsH[BM][APITCH], AsL[BM][APITCH];  // 16 packed-K words + pad
    __shared__ uint32_t WsH[16][72], WsL[16][72];          // permuted cols, pitch 72

    int tid  = threadIdx.x;
    int warp = tid >> 5;
    int lane = tid & 31;
    int g    = lane >> 2;
    int t4   = lane & 3;
    int warpM = warp >> 1;  // 0..3
    int warpN = warp & 1;   // 0..1

    int m0 = blockIdx.x * BM;
    int n0 = blockIdx.y * BN;

    uint32_t asHbase = (uint32_t)__cvta_generic_to_shared(&AsH[0][0]);
    uint32_t asLbase = (uint32_t)__cvta_generic_to_shared(&AsL[0][0]);
    int lrow  = lane & 15;
    int lcolw = (lane >> 4) * 4;

    float acc[2][4][4];
#pragma unroll
    for (int i = 0; i < 2; i++)
#pragma unroll
        for (int j = 0; j < 4; j++)
#pragma unroll
            for (int k = 0; k < 4; k++) acc[i][j][k] = 0.f;

    for (int kb = 0; kb < 128; kb += BK) {
        int kb2 = kb >> 1;
        // ---- A tile 128x32 fp32: 4 float4/thread; split+pack to bf16 hi/lo ----
#pragma unroll
        for (int i = 0; i < 4; i++) {
            int f   = i * 256 + tid;
            int row = f >> 3;
            int cg  = f & 7;
            int m   = m0 + row;
            float4 v = make_float4(0.f, 0.f, 0.f, 0.f);
            if (m < M) v = *(const float4*)&A[(size_t)m * 128 + kb + cg * 4];
            uint32_t h0 = pack_bf16x2(v.x, v.y);
            uint32_t h1 = pack_bf16x2(v.z, v.w);
            uint32_t l0 = pack_bf16x2(v.x - lo_as_f32(h0), v.y - hi_as_f32(h0));
            uint32_t l1 = pack_bf16x2(v.z - lo_as_f32(h1), v.w - hi_as_f32(h1));
            AsH[row][cg * 2]     = h0;
            AsH[row][cg * 2 + 1] = h1;
            AsL[row][cg * 2]     = l0;
            AsL[row][cg * 2 + 1] = l1;
        }
        // ---- W tile: 16 rows x 64 words, straight uint4 copy (pre-permuted) ----
        {
            int pk = tid >> 4;
            int cg = tid & 15;
            *(uint4*)&WsH[pk][cg * 4] = *(const uint4*)&WH[(size_t)(kb2 + pk) * ldww + n0 + cg * 4];
            *(uint4*)&WsL[pk][cg * 4] = *(const uint4*)&WL[(size_t)(kb2 + pk) * ldww + n0 + cg * 4];
        }
        __syncthreads();

#pragma unroll
        for (int ks = 0; ks < 2; ks++) {
            int kp = ks * 8;
            // A fragments: one ldmatrix.x4 per (mt, image)
            uint32_t ah[2][4], al[2][4];
#pragma unroll
            for (int mt = 0; mt < 2; mt++) {
                int rb = warpM * 32 + mt * 16;
                uint32_t off = (uint32_t)(((rb + lrow) * APITCH + kp + lcolw) * 4);
                ldsm_x4(ah[mt], asHbase + off);
                ldsm_x4(al[mt], asLbase + off);
            }
            // B fragments: 4 n-tiles per v4 load (permuted layout)
            int colw = g * 8 + warpN * 4;
            uint4 bh0 = *(const uint4*)&WsH[kp + t4][colw];
            uint4 bh1 = *(const uint4*)&WsH[kp + t4 + 4][colw];
            uint4 bl0 = *(const uint4*)&WsL[kp + t4][colw];
            uint4 bl1 = *(const uint4*)&WsL[kp + t4 + 4][colw];
            const uint32_t* ph0 = (const uint32_t*)&bh0;
            const uint32_t* ph1 = (const uint32_t*)&bh1;
            const uint32_t* pl0 = (const uint32_t*)&bl0;
            const uint32_t* pl1 = (const uint32_t*)&bl1;
#pragma unroll
            for (int nt = 0; nt < 4; nt++) {
                uint32_t bh[2] = {ph0[nt], ph1[nt]};
                uint32_t bl[2] = {pl0[nt], pl1[nt]};
#pragma unroll
                for (int mt = 0; mt < 2; mt++) {
                    mma_bf16(acc[mt][nt], ah[mt], bh);
                    mma_bf16(acc[mt][nt], ah[mt], bl);
                    mma_bf16(acc[mt][nt], al[mt], bh);
                }
            }
        }
        __syncthreads();
    }

    // ---- epilogue: bias + store ----
#pragma unroll
    for (int mt = 0; mt < 2; mt++) {
#pragma unroll
        for (int nt = 0; nt < 4; nt++) {
            int col = n0 + warpN * 32 + nt * 8 + t4 * 2;
            float b0 = bias[col], b1 = bias[col + 1];
            int r0 = m0 + warpM * 32 + mt * 16 + g;
            int r1 = r0 + 8;
            if (OUT_BF16) {
                if (r0 < M)
                    Cw[(size_t)r0 * ldcw + (col >> 1)] = pack_bf16x2(acc[mt][nt][0] + b0, acc[mt][nt][1] + b1);
                if (r1 < M)
                    Cw[(size_t)r1 * ldcw + (col >> 1)] = pack_bf16x2(acc[mt][nt][2] + b0, acc[mt][nt][3] + b1);
            } else {
                float* C = (float*)Cw;
                if (r0 < M) {
                    float2 v = make_float2(acc[mt][nt][0] + b0, acc[mt][nt][1] + b1);
                    *(float2*)&C[(size_t)r0 * ldcw + col] = v;
                }
                if (r1 < M) {
                    float2 v = make_float2(acc[mt][nt][2] + b0, acc[mt][nt][3] + b1);
                    *(float2*)&C[(size_t)r1 * ldcw + col] = v;
                }
            }
        }
    }
}

// ---------------------------------------------------------------------------
// Build fused per-type fp32 weights WCAT[t][128][640] and biases BCAT[t][640]:
// cols [0,128)=K_rA, [128,256)=K_rB, [256,384)=V_rA, [384,512)=V_rB, [512,640)=Q
//   t=0: rA=0, rB=2 ;  t=1: rA=1, rB=3
// ---------------------------------------------------------------------------
__global__ void prep_wcat(const float* __restrict__ Wk, const float* __restrict__ bk,
                          const float* __restrict__ Wq, const float* __restrict__ bq,
                          const float* __restrict__ Wv, const float* __restrict__ bv,
                          const float* __restrict__ rel_att, const float* __restrict__ rel_msg) {
    int idx = blockIdx.x * blockDim.x + threadIdx.x;
    if (idx >= 2 * 128 * NC) return;
    int t = idx / (128 * NC);
    int i = (idx / NC) & 127;
    int c = idx % NC;

    float val, bval = 0.f;
    if (c < 512) {
        int sel = c >> 7;
        int rel = (sel & 1) ? (t == 0 ? 2 : 3) : (t == 0 ? 0 : 1);
        int isV = sel >> 1;
        int o = c & 127, h = o >> 4, eo = o & 15;
        const float* Wsrc = (isV ? Wv : Wk) + (size_t)t * 16384 + (size_t)i * 128 + h * 16;
        const float* bsrc = (isV ? bv : bk) + t * 128 + h * 16;
        const float* R = (isV ? rel_msg : rel_att) + (((size_t)rel * 8 + h) * 16) * 16 + eo;
        float a = 0.f, b = 0.f;
#pragma unroll
        for (int d = 0; d < 16; d++) {
            a += Wsrc[d] * R[d * 16];
            b += bsrc[d] * R[d * 16];
        }
        val = a; bval = b;
    } else {
        int o = c - 512;
        val = Wq[(size_t)t * 16384 + (size_t)i * 128 + o];
        bval = bq[t * 128 + o];
    }
    g_buf[OFF_WCAT + (size_t)t * 128 * NC + (size_t)i * NC + c] = val;
    if (i == 0) g_buf[OFF_BCAT + t * NC + c] = bval;
}

// ---------------------------------------------------------------------------
// Pack fp32 weights into bf16 hi/lo images, packed pairs along K, columns
// permuted within 64-groups so the GEMM B-fragment reads are v4 LDS.
// ---------------------------------------------------------------------------
__global__ void pack_weights(const float* __restrict__ Wa) {
    uint32_t* W32 = (uint32_t*)g_buf;
    int idx = blockIdx.x * blockDim.x + threadIdx.x;
    int n_cat = 2 * 64 * NC;
    int n_wa  = 2 * 64 * 128;
    if (idx < n_cat) {
        int t  = idx / (64 * NC);
        int pk = (idx / NC) & 63;
        int n  = idx % NC;
        const float* Wt = g_buf + OFF_WCAT + (size_t)t * 128 * NC;
        float w0 = Wt[(size_t)(2 * pk)     * NC + n];
        float w1 = Wt[(size_t)(2 * pk + 1) * NC + n];
        uint32_t h = pack_bf16x2(w0, w1);
        uint32_t l = pack_bf16x2(w0 - lo_as_f32(h), w1 - hi_as_f32(h));
        int p = wperm(n);
        W32[OFF_WH + (size_t)t * 64 * NC + (size_t)pk * NC + p] = h;
        W32[OFF_WL + (size_t)t * 64 * NC + (size_t)pk * NC + p] = l;
    } else if (idx < n_cat + n_wa) {
        int j  = idx - n_cat;
        int t  = j / (64 * 128);
        int pk = (j / 128) & 63;
        int n  = j % 128;
        float w0 = Wa[(size_t)t * 16384 + (size_t)(2 * pk)     * 128 + n];
        float w1 = Wa[(size_t)t * 16384 + (size_t)(2 * pk + 1) * 128 + n];
        uint32_t h = pack_bf16x2(w0, w1);
        uint32_t l = pack_bf16x2(w0 - lo_as_f32(h), w1 - hi_as_f32(h));
        int p = wperm(n);
        W32[OFF_WAH + (size_t)t * 64 * 128 + (size_t)pk * 128 + p] = h;
        W32[OFF_WAL + (size_t)t * 64 * 128 + (size_t)pk * 128 + p] = l;
    }
}

// ---------------------------------------------------------------------------
// Zero NUM and DEN
// ---------------------------------------------------------------------------
__global__ void zero_accum() {
    size_t n = (size_t)4 * NN * 128 + (size_t)4 * NN * 8;
    size_t i = (size_t)blockIdx.x * blockDim.x + threadIdx.x;
    size_t stride = (size_t)gridDim.x * blockDim.x;
    for (; i < n; i += stride) g_buf[OFF_NUM + i] = 0.f;
}

// ---------------------------------------------------------------------------
// Single edge pass over bf16 projections:
// score -> exp -> den += ex -> num += ex * V[src].  One warp per edge.
// ---------------------------------------------------------------------------
__global__ void edge_pass(const float* __restrict__ pri,
                          const int* __restrict__ s0, const int* __restrict__ d0,
                          const int* __restrict__ s1, const int* __restrict__ d1,
                          const int* __restrict__ s2, const int* __restrict__ d2,
                          const int* __restrict__ s3, const int* __restrict__ d3) {
    int r = blockIdx.y;
    int e = blockIdx.x * (blockDim.x >> 5) + (threadIdx.x >> 5);
    if (e >= EE) return;
    int lane = threadIdx.x & 31;

    const int* src = (r == 0) ? s0 : (r == 1) ? s1 : (r == 2) ? s2 : s3;
    const int* dst = (r == 0) ? d0 : (r == 1) ? d1 : (r == 2) ? d2 : d3;
    int st = r & 1;
    int dt = (r == 0 || r == 3) ? 1 : 0;
    int sliceKVw = (r >> 1) * 64;   // K words at sliceKVw, V at 128+sliceKVw, Q at 256

    int s = src[e];
    int d = dst[e];

    const uint32_t* Cw = (const uint32_t*)g_buf;
    const uint32_t* Cs = Cw + (st ? OFF_C1 : OFF_C0) + (size_t)s * NCW;
    const uint32_t* Cd = Cw + (dt ? OFF_C1 : OFF_C0) + (size_t)d * NCW;

    uint2 qw = *(const uint2*)&Cd[256 + lane * 2];
    uint2 kw = *(const uint2*)&Cs[sliceKVw + lane * 2];
    float p = lo_as_f32(qw.x) * lo_as_f32(kw.x) + hi_as_f32(qw.x) * hi_as_f32(kw.x)
            + lo_as_f32(qw.y) * lo_as_f32(kw.y) + hi_as_f32(qw.y) * hi_as_f32(kw.y);
    p += __shfl_xor_sync(0xffffffffu, p, 1);
    p += __shfl_xor_sync(0xffffffffu, p, 2);
    int h = lane >> 2;
    float sc = p * pri[r * 8 + h] * 0.25f;   // 1/sqrt(16)
    float ex = __expf(sc);

    if ((lane & 3) == 0) {
        float* dp = g_buf + OFF_DEN + ((size_t)r * NN + d) * 8 + h;
        asm volatile("red.global.add.f32 [%0], %1;" :: "l"(dp), "f"(ex) : "memory");
    }

    uint2 vw = *(const uint2*)&Cs[128 + sliceKVw + lane * 2];
    float* np = g_buf + OFF_NUM + ((size_t)r * NN + d) * 128 + lane * 4;
    asm volatile("red.global.add.v4.f32 [%0], {%1,%2,%3,%4};"
                 :: "l"(np),
                    "f"(lo_as_f32(vw.x) * ex), "f"(hi_as_f32(vw.x) * ex),
                    "f"(lo_as_f32(vw.y) * ex), "f"(hi_as_f32(vw.y) * ex)
                 : "memory");
}

// ---------------------------------------------------------------------------
// Node-level normalization + cross-relation mean -> AGG (fp32)
// ---------------------------------------------------------------------------
__global__ void agg_kernel() {
    size_t total = (size_t)2 * NN * 128;
    size_t i = (size_t)blockIdx.x * blockDim.x + threadIdx.x;
    size_t stride = (size_t)gridDim.x * blockDim.x;
    for (; i < total; i += stride) {
        int j = (int)(i & 127);
        size_t nt = i >> 7;
        int t = (int)(nt / NN);
        int n = (int)(nt % NN);
        int rA = (t == 0) ? 1 : 0;
        int rB = (t == 0) ? 2 : 3;
        int h = j >> 4;
        float a = 0.f;
        float dA = g_buf[OFF_DEN + ((size_t)rA * NN + n) * 8 + h];
        if (dA > 0.f) a += g_buf[OFF_NUM + ((size_t)rA * NN + n) * 128 + j] / dA;
        float dB = g_buf[OFF_DEN + ((size_t)rB * NN + n) * 8 + h];
        if (dB > 0.f) a += g_buf[OFF_NUM + ((size_t)rB * NN + n) * 128 + j] / dB;
        g_buf[OFF_AGG + i] = 0.5f * a;
    }
}

// ---------------------------------------------------------------------------
// Skip + LayerNorm. One warp per row.
// ---------------------------------------------------------------------------
__global__ void ln_kernel(const float* __restrict__ h0, const float* __restrict__ h1,
                          const float* __restrict__ skip,
                          const float* __restrict__ ln_g, const float* __restrict__ ln_b,
                          float* __restrict__ out) {
    int warp = (blockIdx.x * blockDim.x + threadIdx.x) >> 5;
    int lane = threadIdx.x & 31;
    if (warp >= 2 * NN) return;
    int t = warp / NN;
    int n = warp % NN;

    const float* hh = (t == 0) ? h0 : h1;
    const float* tr = g_buf + OFF_TRANS + ((size_t)t * NN + n) * 128;
    float alpha = 1.f / (1.f + __expf(-skip[t]));
    float beta = 1.f - alpha;

    float4 tv = *(const float4*)&tr[lane * 4];
    float4 hv = *(const float4*)&hh[(size_t)n * 128 + lane * 4];
    float4 x;
    x.x = tv.x * alpha + hv.x * beta;
    x.y = tv.y * alpha + hv.y * beta;
    x.z = tv.z * alpha + hv.z * beta;
    x.w = tv.w * alpha + hv.w * beta;

    float s1 = x.x + x.y + x.z + x.w;
    float s2 = x.x * x.x + x.y * x.y + x.z * x.z + x.w * x.w;
#pragma unroll
    for (int o = 16; o >= 1; o >>= 1) {
        s1 += __shfl_xor_sync(0xffffffffu, s1, o);
        s2 += __shfl_xor_sync(0xffffffffu, s2, o);
    }
    float mean = s1 * (1.f / 128.f);
    float var  = s2 * (1.f / 128.f) - mean * mean;
    float rstd = rsqrtf(var + 1e-5f);

    int j = lane * 4;
    float4 g4 = *(const float4*)&ln_g[t * 128 + j];
    float4 b4 = *(const float4*)&ln_b[t * 128 + j];
    float4 o4;
    o4.x = (x.x - mean) * rstd * g4.x + b4.x;
    o4.y = (x.y - mean) * rstd * g4.y + b4.y;
    o4.z = (x.z - mean) * rstd * g4.z + b4.z;
    o4.w = (x.w - mean) * rstd * g4.w + b4.w;
    *(float4*)&out[((size_t)t * NN + n) * 128 + j] = o4;
}

// ---------------------------------------------------------------------------
// Host launcher
// ---------------------------------------------------------------------------
extern "C" void kernel_launch(void* const* d_in, const int* in_sizes, int n_in,
                              void* d_out, int out_size) {
    const float* h0 = (const float*)d_in[0];
    const float* h1 = (const float*)d_in[1];
    const int* s0 = (const int*)d_in[2];
    const int* d0 = (const int*)d_in[3];
    const int* s1 = (const int*)d_in[4];
    const int* d1 = (const int*)d_in[5];
    const int* s2 = (const int*)d_in[6];
    const int* d2 = (const int*)d_in[7];
    const int* s3 = (const int*)d_in[8];
    const int* d3 = (const int*)d_in[9];
    const float* Wk = (const float*)d_in[10];
    const float* bk = (const float*)d_in[11];
    const float* Wq = (const float*)d_in[12];
    const float* bq = (const float*)d_in[13];
    const float* Wv = (const float*)d_in[14];
    const float* bv = (const float*)d_in[15];
    const float* Wa = (const float*)d_in[16];
    const float* ba = (const float*)d_in[17];
    const float* rel_att = (const float*)d_in[18];
    const float* rel_msg = (const float*)d_in[19];
    const float* rel_pri = (const float*)d_in[20];
    const float* skip = (const float*)d_in[21];
    const float* ln_g = (const float*)d_in[22];
    const float* ln_b = (const float*)d_in[23];

    static float* buf = nullptr;
    if (!buf) cudaGetSymbolAddress((void**)&buf, g_buf);
    uint32_t* buf32 = (uint32_t*)buf;

    // 1) fused fp32 weights -> bf16 hi/lo packed+permuted images; zero accum
    prep_wcat<<<(2 * 128 * NC + 255) / 256, 256>>>(Wk, bk, Wq, bq, Wv, bv, rel_att, rel_msg);
    pack_weights<<<(2 * 64 * NC + 2 * 64 * 128 + 255) / 256, 256>>>(Wa);
    zero_accum<<<2048, 256>>>();

    // 2) fused KVQ projections: per type, [NN,128] x [128,640] -> bf16 packed
    int mblocks = (NN + BM - 1) / BM;
    const float* hs[2] = {h0, h1};
    for (int t = 0; t < 2; t++) {
        dim3 gg(mblocks, NC / BN);
        gemm3<true><<<gg, 256>>>(hs[t],
                                 buf32 + OFF_WH + (size_t)t * 64 * NC,
                                 buf32 + OFF_WL + (size_t)t * 64 * NC, NC,
                                 buf + OFF_BCAT + t * NC,
                                 buf32 + (t ? OFF_C1 : OFF_C0), NCW, NN);
    }

    // 3) single edge pass (scores + softmax accumulation)
    dim3 gE((EE + 7) / 8, 4);
    edge_pass<<<gE, 256>>>(rel_pri, s0, d0, s1, d1, s2, d2, s3, d3);

    // 4) normalize + cross-relation mean
    agg_kernel<<<2048, 256>>>();

    // 5) output projection [NN,128] x [128,128] per type (fp32 out)
    for (int t = 0; t < 2; t++) {
        dim3 gg(mblocks, 128 / BN);
        gemm3<false><<<gg, 256>>>(buf + OFF_AGG + (size_t)t * NN * 128,
                                  buf32 + OFF_WAH + (size_t)t * 64 * 128,
                                  buf32 + OFF_WAL + (size_t)t * 64 * 128, 128,
                                  ba + t * 128,
                                  (uint32_t*)(buf + OFF_TRANS + (size_t)t * NN * 128), 128, NN);
    }

    // 6) skip + layernorm -> out
    ln_kernel<<<(2 * NN * 32 + 255) / 256, 256>>>(h0, h1, skip, ln_g, ln_b, (float*)d_out);
}

// round 8
// speedup vs baseline: 2.6377x; 1.1097x over previous
#include <cuda_runtime.h>
#include <cuda_bf16.h>
#include <cstdint>
#include <math.h>

// ---------------------------------------------------------------------------
// Problem constants
// ---------------------------------------------------------------------------
#define NN 50000      // nodes per type
#define EE 200000     // edges per relation
// REL = [(0,1),(1,0),(0,0),(1,1)]
#define NC 640        // fused projection width: [K_rA | K_rB | V_rA | V_rB | Q]
#define NCW 320       // bf16-packed row width in 32-bit words

// ---------------------------------------------------------------------------
// Scratch layout (32-bit words)
// ---------------------------------------------------------------------------
constexpr size_t OFF_C0    = 0;                                  // NN*320 (bf16x2)
constexpr size_t OFF_C1    = OFF_C0    + (size_t)NN * NCW;
constexpr size_t OFF_NUM   = OFF_C1    + (size_t)NN * NCW;       // 4*NN*128 fp32
constexpr size_t OFF_DEN   = OFF_NUM   + (size_t)4 * NN * 128;   // 4*NN*8 fp32
constexpr size_t OFF_TRANS = OFF_DEN   + (size_t)4 * NN * 8;     // 2*NN*128 fp32
constexpr size_t OFF_AGGH  = OFF_TRANS + (size_t)2 * NN * 128;   // 2*NN*64 bf16x2
constexpr size_t OFF_AGGL  = OFF_AGGH  + (size_t)2 * NN * 64;    // 2*NN*64
constexpr size_t OFF_XH    = OFF_AGGL  + (size_t)2 * NN * 64;    // 2*NN*64 (h packed hi)
constexpr size_t OFF_XL    = OFF_XH    + (size_t)2 * NN * 64;    // 2*NN*64
constexpr size_t OFF_WCAT  = OFF_XL    + (size_t)2 * NN * 64;    // 2*128*640 fp32
constexpr size_t OFF_BCAT  = OFF_WCAT  + (size_t)2 * 128 * NC;   // 2*640 fp32
constexpr size_t OFF_WH    = OFF_BCAT  + (size_t)2 * NC;         // 2*64*640
constexpr size_t OFF_WL    = OFF_WH    + (size_t)2 * 64 * NC;
constexpr size_t OFF_WAH   = OFF_WL    + (size_t)2 * 64 * NC;    // 2*64*128
constexpr size_t OFF_WAL   = OFF_WAH   + (size_t)2 * 64 * 128;
constexpr size_t BUF_TOTAL = OFF_WAL   + (size_t)2 * 64 * 128;

__device__ float g_buf[BUF_TOTAL];

// ---------------------------------------------------------------------------
// helpers
// ---------------------------------------------------------------------------
__device__ __forceinline__ uint32_t pack_bf16x2(float x, float y) {
    uint32_t r;
    asm("cvt.rn.bf16x2.f32 %0, %1, %2;" : "=r"(r) : "f"(y), "f"(x));
    return r;
}
__device__ __forceinline__ float lo_as_f32(uint32_t p) { return __uint_as_float(p << 16); }
__device__ __forceinline__ float hi_as_f32(uint32_t p) { return __uint_as_float(p & 0xffff0000u); }

__device__ __forceinline__ void mma_bf16(float* c, const uint32_t* a, const uint32_t* b) {
    asm volatile(
        "mma.sync.aligned.m16n8k16.row.col.f32.bf16.bf16.f32 "
        "{%0,%1,%2,%3}, {%4,%5,%6,%7}, {%8,%9}, {%0,%1,%2,%3};"
        : "+f"(c[0]), "+f"(c[1]), "+f"(c[2]), "+f"(c[3])
        : "r"(a[0]), "r"(a[1]), "r"(a[2]), "r"(a[3]), "r"(b[0]), "r"(b[1]));
}

__device__ __forceinline__ void ldsm_x4(uint32_t* r, uint32_t addr) {
    asm volatile("ldmatrix.sync.aligned.m8n8.x4.shared.b16 {%0,%1,%2,%3}, [%4];"
                 : "=r"(r[0]), "=r"(r[1]), "=r"(r[2]), "=r"(r[3]) : "r"(addr));
}

__device__ __forceinline__ void cp_async16(uint32_t dst, const void* src, int srcbytes) {
    asm volatile("cp.async.cg.shared.global [%0], [%1], 16, %2;"
                 :: "r"(dst), "l"(src), "r"(srcbytes) : "memory");
}

// column permutation within each 64-col group (word-granular)
__host__ __device__ __forceinline__ int wperm(int n) {
    return (n & ~63) | (((n & 7) << 3) | ((n >> 3) & 7));
}

// ---------------------------------------------------------------------------
// 3xBF16 tensor-core GEMM, pre-packed A: C[M,*] = A[M,128] @ W[128,ldw] + bias
// A given as bf16 hi/lo packed images (64 words per row). W pre-split +
// pre-permuted. Double-buffered cp.async pipeline, dynamic smem.
// BM=128, BN=64, BK=32, 256 threads (8 warps 4x2), warp tile 32x32.
// ---------------------------------------------------------------------------
#define BM 128
#define BN 64
#define APITCH 20
#define A_STG (BM * APITCH)        // 2560 words
#define W_STG (16 * 72)            // 1152 words
#define GSMEM_WORDS (4 * A_STG + 4 * W_STG)
#define GSMEM_BYTES (GSMEM_WORDS * 4)

template<bool OUT_BF16>
__global__ __launch_bounds__(256, 2) void gemm3(const uint32_t* __restrict__ AH,
                                                const uint32_t* __restrict__ AL,
                                                const uint32_t* __restrict__ WH,
                                                const uint32_t* __restrict__ WL,
                                                int ldww,
                                                const float* __restrict__ bias,
                                                uint32_t* __restrict__ Cw, int ldcw,
                                                int M) {
    extern __shared__ uint32_t sm[];
    // layout: AsH[2 stages], AsL[2], WsH[2], WsL[2]
    uint32_t smbase = (uint32_t)__cvta_generic_to_shared(sm);

    int tid  = threadIdx.x;
    int warp = tid >> 5;
    int lane = tid & 31;
    int g    = lane >> 2;
    int t4   = lane & 3;
    int warpM = warp >> 1;
    int warpN = warp & 1;

    int m0 = blockIdx.x * BM;
    int n0 = blockIdx.y * BN;

    int lrow  = lane & 15;
    int lcolw = (lane >> 4) * 4;

    float acc[2][4][4];
#pragma unroll
    for (int i = 0; i < 2; i++)
#pragma unroll
        for (int j = 0; j < 4; j++)
#pragma unroll
            for (int k = 0; k < 4; k++) acc[i][j][k] = 0.f;

    // ---- stage loader (cp.async) ----
    auto stage_load = [&](int s, int kb) {
        int kb2 = kb >> 1;
#pragma unroll
        for (int i = 0; i < 2; i++) {
            int c   = i * 256 + tid;
            int row = c >> 2;
            int cw  = (c & 3) * 4;
            int m   = m0 + row;
            int ok  = (m < M) ? 16 : 0;
            size_t srcoff = (size_t)(m < M ? m : M - 1) * 64 + kb2 + cw;
            uint32_t dH = smbase + (uint32_t)((s * A_STG + row * APITCH + cw) * 4);
            uint32_t dL = smbase + (uint32_t)(((2 + s) * A_STG + row * APITCH + cw) * 4);
            cp_async16(dH, AH + srcoff, ok);
            cp_async16(dL, AL + srcoff, ok);
        }
        {
            int pk = tid >> 4;
            int cg = tid & 15;
            size_t srcoff = (size_t)(kb2 + pk) * ldww + n0 + cg * 4;
            uint32_t dH = smbase + (uint32_t)((4 * A_STG + s * W_STG + pk * 72 + cg * 4) * 4);
            uint32_t dL = smbase + (uint32_t)((4 * A_STG + (2 + s) * W_STG + pk * 72 + cg * 4) * 4);
            cp_async16(dH, WH + srcoff, 16);
            cp_async16(dL, WL + srcoff, 16);
        }
        asm volatile("cp.async.commit_group;" ::: "memory");
    };

    stage_load(0, 0);

    int s = 0;
    for (int kb = 0; kb < 128; kb += 32, s ^= 1) {
        if (kb + 32 < 128) {
            stage_load(s ^ 1, kb + 32);
            asm volatile("cp.async.wait_group 1;" ::: "memory");
        } else {
            asm volatile("cp.async.wait_group 0;" ::: "memory");
        }
        __syncthreads();

        uint32_t asHs = smbase + (uint32_t)(s * A_STG * 4);
        uint32_t asLs = smbase + (uint32_t)((2 + s) * A_STG * 4);
        const uint32_t* wsH = sm + 4 * A_STG + s * W_STG;
        const uint32_t* wsL = sm + 4 * A_STG + (2 + s) * W_STG;

#pragma unroll
        for (int ks = 0; ks < 2; ks++) {
            int kp = ks * 8;
            uint32_t ah[2][4], al[2][4];
#pragma unroll
            for (int mt = 0; mt < 2; mt++) {
                int rb = warpM * 32 + mt * 16;
                uint32_t off = (uint32_t)(((rb + lrow) * APITCH + kp + lcolw) * 4);
                ldsm_x4(ah[mt], asHs + off);
                ldsm_x4(al[mt], asLs + off);
            }
            int colw = g * 8 + warpN * 4;
            uint4 bh0 = *(const uint4*)&wsH[(kp + t4) * 72 + colw];
            uint4 bh1 = *(const uint4*)&wsH[(kp + t4 + 4) * 72 + colw];
            uint4 bl0 = *(const uint4*)&wsL[(kp + t4) * 72 + colw];
            uint4 bl1 = *(const uint4*)&wsL[(kp + t4 + 4) * 72 + colw];
            const uint32_t* ph0 = (const uint32_t*)&bh0;
            const uint32_t* ph1 = (const uint32_t*)&bh1;
            const uint32_t* pl0 = (const uint32_t*)&bl0;
            const uint32_t* pl1 = (const uint32_t*)&bl1;
#pragma unroll
            for (int nt = 0; nt < 4; nt++) {
                uint32_t bh[2] = {ph0[nt], ph1[nt]};
                uint32_t bl[2] = {pl0[nt], pl1[nt]};
#pragma unroll
                for (int mt = 0; mt < 2; mt++) {
                    mma_bf16(acc[mt][nt], ah[mt], bh);
                    mma_bf16(acc[mt][nt], ah[mt], bl);
                    mma_bf16(acc[mt][nt], al[mt], bh);
                }
            }
        }
        __syncthreads();
    }

    // ---- epilogue: bias + store ----
#pragma unroll
    for (int mt = 0; mt < 2; mt++) {
#pragma unroll
        for (int nt = 0; nt < 4; nt++) {
            int col = n0 + warpN * 32 + nt * 8 + t4 * 2;
            float b0 = bias[col], b1 = bias[col + 1];
            int r0 = m0 + warpM * 32 + mt * 16 + g;
            int r1 = r0 + 8;
            if (OUT_BF16) {
                if (r0 < M)
                    Cw[(size_t)r0 * ldcw + (col >> 1)] = pack_bf16x2(acc[mt][nt][0] + b0, acc[mt][nt][1] + b1);
                if (r1 < M)
                    Cw[(size_t)r1 * ldcw + (col >> 1)] = pack_bf16x2(acc[mt][nt][2] + b0, acc[mt][nt][3] + b1);
            } else {
                float* C = (float*)Cw;
                if (r0 < M) {
                    float2 v = make_float2(acc[mt][nt][0] + b0, acc[mt][nt][1] + b1);
                    *(float2*)&C[(size_t)r0 * ldcw + col] = v;
                }
                if (r1 < M) {
                    float2 v = make_float2(acc[mt][nt][2] + b0, acc[mt][nt][3] + b1);
                    *(float2*)&C[(size_t)r1 * ldcw + col] = v;
                }
            }
        }
    }
}

// ---------------------------------------------------------------------------
// Build fused per-type fp32 weights WCAT[t][128][640] and biases BCAT[t][640]
// ---------------------------------------------------------------------------
__global__ void prep_wcat(const float* __restrict__ Wk, const float* __restrict__ bk,
                          const float* __restrict__ Wq, const float* __restrict__ bq,
                          const float* __restrict__ Wv, const float* __restrict__ bv,
                          const float* __restrict__ rel_att, const float* __restrict__ rel_msg) {
    int idx = blockIdx.x * blockDim.x + threadIdx.x;
    if (idx >= 2 * 128 * NC) return;
    int t = idx / (128 * NC);
    int i = (idx / NC) & 127;
    int c = idx % NC;

    float val, bval = 0.f;
    if (c < 512) {
        int sel = c >> 7;
        int rel = (sel & 1) ? (t == 0 ? 2 : 3) : (t == 0 ? 0 : 1);
        int isV = sel >> 1;
        int o = c & 127, h = o >> 4, eo = o & 15;
        const float* Wsrc = (isV ? Wv : Wk) + (size_t)t * 16384 + (size_t)i * 128 + h * 16;
        const float* bsrc = (isV ? bv : bk) + t * 128 + h * 16;
        const float* R = (isV ? rel_msg : rel_att) + (((size_t)rel * 8 + h) * 16) * 16 + eo;
        float a = 0.f, b = 0.f;
#pragma unroll
        for (int d = 0; d < 16; d++) {
            a += Wsrc[d] * R[d * 16];
            b += bsrc[d] * R[d * 16];
        }
        val = a; bval = b;
    } else {
        int o = c - 512;
        val = Wq[(size_t)t * 16384 + (size_t)i * 128 + o];
        bval = bq[t * 128 + o];
    }
    g_buf[OFF_WCAT + (size_t)t * 128 * NC + (size_t)i * NC + c] = val;
    if (i == 0) g_buf[OFF_BCAT + t * NC + c] = bval;
}

// ---------------------------------------------------------------------------
// Pack weights: fp32 -> bf16 hi/lo, pairs along K, cols permuted in 64-groups
// ---------------------------------------------------------------------------
__global__ void pack_weights(const float* __restrict__ Wa) {
    uint32_t* W32 = (uint32_t*)g_buf;
    int idx = blockIdx.x * blockDim.x + threadIdx.x;
    int n_cat = 2 * 64 * NC;
    int n_wa  = 2 * 64 * 128;
    if (idx < n_cat) {
        int t  = idx / (64 * NC);
        int pk = (idx / NC) & 63;
        int n  = idx % NC;
        const float* Wt = g_buf + OFF_WCAT + (size_t)t * 128 * NC;
        float w0 = Wt[(size_t)(2 * pk)     * NC + n];
        float w1 = Wt[(size_t)(2 * pk + 1) * NC + n];
        uint32_t h = pack_bf16x2(w0, w1);
        uint32_t l = pack_bf16x2(w0 - lo_as_f32(h), w1 - hi_as_f32(h));
        int p = wperm(n);
        W32[OFF_WH + (size_t)t * 64 * NC + (size_t)pk * NC + p] = h;
        W32[OFF_WL + (size_t)t * 64 * NC + (size_t)pk * NC + p] = l;
    } else if (idx < n_cat + n_wa) {
        int j  = idx - n_cat;
        int t  = j / (64 * 128);
        int pk = (j / 128) & 63;
        int n  = j % 128;
        float w0 = Wa[(size_t)t * 16384 + (size_t)(2 * pk)     * 128 + n];
        float w1 = Wa[(size_t)t * 16384 + (size_t)(2 * pk + 1) * 128 + n];
        uint32_t h = pack_bf16x2(w0, w1);
        uint32_t l = pack_bf16x2(w0 - lo_as_f32(h), w1 - hi_as_f32(h));
        int p = wperm(n);
        W32[OFF_WAH + (size_t)t * 64 * 128 + (size_t)pk * 128 + p] = h;
        W32[OFF_WAL + (size_t)t * 64 * 128 + (size_t)pk * 128 + p] = l;
    }
}

// ---------------------------------------------------------------------------
// Pack node features h0/h1 -> bf16 hi/lo images (64 words per row)
// ---------------------------------------------------------------------------
__global__ void pack_x(const float* __restrict__ h0, const float* __restrict__ h1) {
    uint32_t* W32 = (uint32_t*)g_buf;
    int idx = blockIdx.x * blockDim.x + threadIdx.x;
    int total = 2 * NN * 64;
    if (idx >= total) return;
    int t = idx / (NN * 64);
    int rem = idx - t * (NN * 64);
    const float* h = t ? h1 : h0;
    float2 v = *(const float2*)&h[(size_t)rem * 2];
    uint32_t hi = pack_bf16x2(v.x, v.y);
    uint32_t lo = pack_bf16x2(v.x - lo_as_f32(hi), v.y - hi_as_f32(hi));
    W32[OFF_XH + (size_t)t * NN * 64 + rem] = hi;
    W32[OFF_XL + (size_t)t * NN * 64 + rem] = lo;
}

// ---------------------------------------------------------------------------
// Zero NUM and DEN
// ---------------------------------------------------------------------------
__global__ void zero_accum() {
    size_t n = (size_t)4 * NN * 128 + (size_t)4 * NN * 8;
    size_t i = (size_t)blockIdx.x * blockDim.x + threadIdx.x;
    size_t stride = (size_t)gridDim.x * blockDim.x;
    for (; i < n; i += stride) g_buf[OFF_NUM + i] = 0.f;
}

// ---------------------------------------------------------------------------
// Single edge pass over bf16 projections. One warp per edge.
// ---------------------------------------------------------------------------
__global__ void edge_pass(const float* __restrict__ pri,
                          const int* __restrict__ s0, const int* __restrict__ d0,
                          const int* __restrict__ s1, const int* __restrict__ d1,
                          const int* __restrict__ s2, const int* __restrict__ d2,
                          const int* __restrict__ s3, const int* __restrict__ d3) {
    int r = blockIdx.y;
    int e = blockIdx.x * (blockDim.x >> 5) + (threadIdx.x >> 5);
    if (e >= EE) return;
    int lane = threadIdx.x & 31;

    const int* src = (r == 0) ? s0 : (r == 1) ? s1 : (r == 2) ? s2 : s3;
    const int* dst = (r == 0) ? d0 : (r == 1) ? d1 : (r == 2) ? d2 : d3;
    int st = r & 1;
    int dt = (r == 0 || r == 3) ? 1 : 0;
    int sliceKVw = (r >> 1) * 64;

    int s = src[e];
    int d = dst[e];

    const uint32_t* Cw = (const uint32_t*)g_buf;
    const uint32_t* Cs = Cw + (st ? OFF_C1 : OFF_C0) + (size_t)s * NCW;
    const uint32_t* Cd = Cw + (dt ? OFF_C1 : OFF_C0) + (size_t)d * NCW;

    uint2 qw = *(const uint2*)&Cd[256 + lane * 2];
    uint2 kw = *(const uint2*)&Cs[sliceKVw + lane * 2];
    float p = lo_as_f32(qw.x) * lo_as_f32(kw.x) + hi_as_f32(qw.x) * hi_as_f32(kw.x)
            + lo_as_f32(qw.y) * lo_as_f32(kw.y) + hi_as_f32(qw.y) * hi_as_f32(kw.y);
    p += __shfl_xor_sync(0xffffffffu, p, 1);
    p += __shfl_xor_sync(0xffffffffu, p, 2);
    int h = lane >> 2;
    float sc = p * pri[r * 8 + h] * 0.25f;
    float ex = __expf(sc);

    if ((lane & 3) == 0) {
        float* dp = g_buf + OFF_DEN + ((size_t)r * NN + d) * 8 + h;
        asm volatile("red.global.add.f32 [%0], %1;" :: "l"(dp), "f"(ex) : "memory");
    }

    uint2 vw = *(const uint2*)&Cs[128 + sliceKVw + lane * 2];
    float* np = g_buf + OFF_NUM + ((size_t)r * NN + d) * 128 + lane * 4;
    asm volatile("red.global.add.v4.f32 [%0], {%1,%2,%3,%4};"
                 :: "l"(np),
                    "f"(lo_as_f32(vw.x) * ex), "f"(hi_as_f32(vw.x) * ex),
                    "f"(lo_as_f32(vw.y) * ex), "f"(hi_as_f32(vw.y) * ex)
                 : "memory");
}

// ---------------------------------------------------------------------------
// Normalize + cross-relation mean, emitting packed bf16 hi/lo AGG images
// ---------------------------------------------------------------------------
__global__ void agg_pack() {
    uint32_t* W32 = (uint32_t*)g_buf;
    size_t total = (size_t)2 * NN * 64;
    size_t i = (size_t)blockIdx.x * blockDim.x + threadIdx.x;
    size_t stride = (size_t)gridDim.x * blockDim.x;
    for (; i < total; i += stride) {
        int w = (int)(i & 63);
        size_t nt = i >> 6;
        int t = (int)(nt / NN);
        int n = (int)(nt % NN);
        int rA = (t == 0) ? 1 : 0;
        int rB = (t == 0) ? 2 : 3;
        int h = w >> 3;
        float dA = g_buf[OFF_DEN + ((size_t)rA * NN + n) * 8 + h];
        float dB = g_buf[OFF_DEN + ((size_t)rB * NN + n) * 8 + h];
        float iA = (dA > 0.f) ? 0.5f / dA : 0.f;
        float iB = (dB > 0.f) ? 0.5f / dB : 0.f;
        const float* nA = g_buf + OFF_NUM + ((size_t)rA * NN + n) * 128 + 2 * w;
        const float* nB = g_buf + OFF_NUM + ((size_t)rB * NN + n) * 128 + 2 * w;
        float2 vA = *(const float2*)nA;
        float2 vB = *(const float2*)nB;
        float a0 = vA.x * iA + vB.x * iB;
        float a1 = vA.y * iA + vB.y * iB;
        uint32_t hi = pack_bf16x2(a0, a1);
        uint32_t lo = pack_bf16x2(a0 - lo_as_f32(hi), a1 - hi_as_f32(hi));
        W32[OFF_AGGH + i] = hi;
        W32[OFF_AGGL + i] = lo;
    }
}

// ---------------------------------------------------------------------------
// Skip + LayerNorm. One warp per row.
// ---------------------------------------------------------------------------
__global__ void ln_kernel(const float* __restrict__ h0, const float* __restrict__ h1,
                          const float* __restrict__ skip,
                          const float* __restrict__ ln_g, const float* __restrict__ ln_b,
                          float* __restrict__ out) {
    int warp = (blockIdx.x * blockDim.x + threadIdx.x) >> 5;
    int lane = threadIdx.x & 31;
    if (warp >= 2 * NN) return;
    int t = warp / NN;
    int n = warp % NN;

    const float* hh = (t == 0) ? h0 : h1;
    const float* tr = g_buf + OFF_TRANS + ((size_t)t * NN + n) * 128;
    float alpha = 1.f / (1.f + __expf(-skip[t]));
    float beta = 1.f - alpha;

    float4 tv = *(const float4*)&tr[lane * 4];
    float4 hv = *(const float4*)&hh[(size_t)n * 128 + lane * 4];
    float4 x;
    x.x = tv.x * alpha + hv.x * beta;
    x.y = tv.y * alpha + hv.y * beta;
    x.z = tv.z * alpha + hv.z * beta;
    x.w = tv.w * alpha + hv.w * beta;

    float s1 = x.x + x.y + x.z + x.w;
    float s2 = x.x * x.x + x.y * x.y + x.z * x.z + x.w * x.w;
#pragma unroll
    for (int o = 16; o >= 1; o >>= 1) {
        s1 += __shfl_xor_sync(0xffffffffu, s1, o);
        s2 += __shfl_xor_sync(0xffffffffu, s2, o);
    }
    float mean = s1 * (1.f / 128.f);
    float var  = s2 * (1.f / 128.f) - mean * mean;
    float rstd = rsqrtf(var + 1e-5f);

    int j = lane * 4;
    float4 g4 = *(const float4*)&ln_g[t * 128 + j];
    float4 b4 = *(const float4*)&ln_b[t * 128 + j];
    float4 o4;
    o4.x = (x.x - mean) * rstd * g4.x + b4.x;
    o4.y = (x.y - mean) * rstd * g4.y + b4.y;
    o4.z = (x.z - mean) * rstd * g4.z + b4.z;
    o4.w = (x.w - mean) * rstd * g4.w + b4.w;
    *(float4*)&out[((size_t)t * NN + n) * 128 + j] = o4;
}

// ---------------------------------------------------------------------------
// Host launcher
// ---------------------------------------------------------------------------
extern "C" void kernel_launch(void* const* d_in, const int* in_sizes, int n_in,
                              void* d_out, int out_size) {
    const float* h0 = (const float*)d_in[0];
    const float* h1 = (const float*)d_in[1];
    const int* s0 = (const int*)d_in[2];
    const int* d0 = (const int*)d_in[3];
    const int* s1 = (const int*)d_in[4];
    const int* d1 = (const int*)d_in[5];
    const int* s2 = (const int*)d_in[6];
    const int* d2 = (const int*)d_in[7];
    const int* s3 = (const int*)d_in[8];
    const int* d3 = (const int*)d_in[9];
    const float* Wk = (const float*)d_in[10];
    const float* bk = (const float*)d_in[11];
    const float* Wq = (const float*)d_in[12];
    const float* bq = (const float*)d_in[13];
    const float* Wv = (const float*)d_in[14];
    const float* bv = (const float*)d_in[15];
    const float* Wa = (const float*)d_in[16];
    const float* ba = (const float*)d_in[17];
    const float* rel_att = (const float*)d_in[18];
    const float* rel_msg = (const float*)d_in[19];
    const float* rel_pri = (const float*)d_in[20];
    const float* skip = (const float*)d_in[21];
    const float* ln_g = (const float*)d_in[22];
    const float* ln_b = (const float*)d_in[23];

    static float* buf = nullptr;
    if (!buf) {
        cudaGetSymbolAddress((void**)&buf, g_buf);
        cudaFuncSetAttribute(gemm3<true>,  cudaFuncAttributeMaxDynamicSharedMemorySize, GSMEM_BYTES);
        cudaFuncSetAttribute(gemm3<false>, cudaFuncAttributeMaxDynamicSharedMemorySize, GSMEM_BYTES);
    }
    uint32_t* buf32 = (uint32_t*)buf;

    // 1) weight prep + feature pack + accumulator zero
    prep_wcat<<<(2 * 128 * NC + 255) / 256, 256>>>(Wk, bk, Wq, bq, Wv, bv, rel_att, rel_msg);
    pack_weights<<<(2 * 64 * NC + 2 * 64 * 128 + 255) / 256, 256>>>(Wa);
    pack_x<<<(2 * NN * 64 + 255) / 256, 256>>>(h0, h1);
    zero_accum<<<2048, 256>>>();

    // 2) fused KVQ projections: per type, [NN,128] x [128,640] -> bf16 packed
    int mblocks = (NN + BM - 1) / BM;
    for (int t = 0; t < 2; t++) {
        dim3 gg(mblocks, NC / BN);
        gemm3<true><<<gg, 256, GSMEM_BYTES>>>(
            buf32 + OFF_XH + (size_t)t * NN * 64,
            buf32 + OFF_XL + (size_t)t * NN * 64,
            buf32 + OFF_WH + (size_t)t * 64 * NC,
            buf32 + OFF_WL + (size_t)t * 64 * NC, NC,
            buf + OFF_BCAT + t * NC,
            buf32 + (t ? OFF_C1 : OFF_C0), NCW, NN);
    }

    // 3) single edge pass
    dim3 gE((EE + 7) / 8, 4);
    edge_pass<<<gE, 256>>>(rel_pri, s0, d0, s1, d1, s2, d2, s3, d3);

    // 4) normalize + mean -> packed AGG images
    agg_pack<<<2048, 256>>>();

    // 5) output projection [NN,128] x [128,128] per type (fp32 out)
    for (int t = 0; t < 2; t++) {
        dim3 gg(mblocks, 128 / BN);
        gemm3<false><<<gg, 256, GSMEM_BYTES>>>(
            buf32 + OFF_AGGH + (size_t)t * NN * 64,
            buf32 + OFF_AGGL + (size_t)t * NN * 64,
            buf32 + OFF_WAH + (size_t)t * 64 * 128,
            buf32 + OFF_WAL + (size_t)t * 64 * 128, 128,
            ba + t * 128,
            (uint32_t*)(buf + OFF_TRANS + (size_t)t * NN * 128), 128, NN);
    }

    // 6) skip + layernorm -> out
    ln_kernel<<<(2 * NN * 32 + 255) / 256, 256>>>(h0, h1, skip, ln_g, ln_b, (float*)d_out);
}